// round 9
// baseline (speedup 1.0000x reference)
#include <cuda_runtime.h>
#include <cuda_bf16.h>
#include <cstdint>

// ---------------------------------------------------------------------------
// Problem constants: B=8, S=512, D_MODEL=1024, H=16, DK=DV=64, BH=128
// ---------------------------------------------------------------------------
#define BB   8
#define SS_  512
#define DM   1024
#define HH   16
#define DKV  64
#define BH   128
#define SCALE 0.125f

// ---------------------------------------------------------------------------
// Scratch (device globals)
// ---------------------------------------------------------------------------
__device__ float g_sc  [(size_t)BH * SS_ * SS_];   // content scores + bias
__device__ float g_sc2 [(size_t)BH * SS_ * SS_];   // edge scores
__device__ float g_ctx [(size_t)BB * SS_ * DM];    // content context
__device__ float g_ctx2[(size_t)BB * SS_ * DM];    // edge context

// projection staging (3-term replicated layout)
__device__ __align__(16) __nv_bfloat16 g_A   [(size_t)4096 * 3072];
__device__ __align__(16) __nv_bfloat16 g_Actx[(size_t)4096 * 3072];
__device__ __align__(16) __nv_bfloat16 g_Bqkv[(size_t)3072 * 3072];
__device__ __align__(16) __nv_bfloat16 g_Bo  [(size_t)1024 * 3072];

// attention operand splits (hi/lo bf16)
__device__ __align__(16) __nv_bfloat16 qh [(size_t)BH * SS_ * DKV];
__device__ __align__(16) __nv_bfloat16 ql [(size_t)BH * SS_ * DKV];
__device__ __align__(16) __nv_bfloat16 kh [(size_t)BH * SS_ * DKV];
__device__ __align__(16) __nv_bfloat16 kl [(size_t)BH * SS_ * DKV];
__device__ __align__(16) __nv_bfloat16 vth[(size_t)BH * DKV * SS_];  // [bh,d,s]
__device__ __align__(16) __nv_bfloat16 vtl[(size_t)BH * DKV * SS_];
__device__ __align__(16) __nv_bfloat16 ekh [(size_t)SS_ * SS_ * DKV]; // [i,j,d]
__device__ __align__(16) __nv_bfloat16 ekl [(size_t)SS_ * SS_ * DKV];
__device__ __align__(16) __nv_bfloat16 evth[(size_t)SS_ * DKV * SS_]; // [i,d,j]
__device__ __align__(16) __nv_bfloat16 evtl[(size_t)SS_ * DKV * SS_];
__device__ __align__(16) __nv_bfloat16 wh [(size_t)BH * SS_ * SS_];   // [bh,i,j]
__device__ __align__(16) __nv_bfloat16 wl [(size_t)BH * SS_ * SS_];

__device__ __forceinline__ uint32_t s2u(const void* p) {
    uint32_t a;
    asm("{ .reg .u64 t; cvta.to.shared.u64 t, %1; cvt.u32.u64 %0, t; }"
        : "=r"(a) : "l"(p));
    return a;
}
__device__ __forceinline__ uint32_t pk2(__nv_bfloat16 a, __nv_bfloat16 b) {
    return (uint32_t)__bfloat16_as_ushort(a) | ((uint32_t)__bfloat16_as_ushort(b) << 16);
}

#define CP_ASYNC16(dst, src) \
    asm volatile("cp.async.cg.shared.global [%0], [%1], 16;" :: "r"(dst), "l"(src) : "memory")
#define CP_COMMIT() asm volatile("cp.async.commit_group;" ::: "memory")
#define CP_WAIT0()  asm volatile("cp.async.wait_group 0;" ::: "memory")

#define LDMATX4(r0, r1, r2, r3, addr) \
    asm volatile("ldmatrix.sync.aligned.m8n8.x4.shared.b16 {%0,%1,%2,%3}, [%4];" \
        : "=r"(r0), "=r"(r1), "=r"(r2), "=r"(r3) : "r"(addr))

#define MMA16816(c, a, b) \
    asm volatile("mma.sync.aligned.m16n8k16.row.col.f32.bf16.bf16.f32 " \
        "{%0,%1,%2,%3}, {%4,%5,%6,%7}, {%8,%9}, {%0,%1,%2,%3};" \
        : "+f"((c)[0]), "+f"((c)[1]), "+f"((c)[2]), "+f"((c)[3]) \
        : "r"((a)[0]), "r"((a)[1]), "r"((a)[2]), "r"((a)[3]), \
          "r"((b)[0]), "r"((b)[1]))

#define LDS_   40                 // padded row stride in bf16 (80 bytes)
#define TILEB  (128 * LDS_ * 2)   // 10240 bytes

// ===========================================================================
// Split conversion: fp32 -> bf16 3-term layout [rows][3072]
// which=0: queries -> g_A (full, ph ignored)
// which=1: g_ctx+g_ctx2 -> g_Actx, rows with s in [ph*256,(ph+1)*256)
// ===========================================================================
__global__ __launch_bounds__(256) void k_split(const float* __restrict__ src_in,
                                               int which, int ph)
{
    int idx = blockIdx.x * 256 + threadIdx.x;
    int c0 = (idx & 127) << 3;
    int r;
    float f[8];
    if (which == 0) {
        r = idx >> 7;
        const float* s = src_in + (size_t)r * 1024 + c0;
        float4 v0 = *(const float4*)(s);
        float4 v1 = *(const float4*)(s + 4);
        f[0]=v0.x; f[1]=v0.y; f[2]=v0.z; f[3]=v0.w;
        f[4]=v1.x; f[5]=v1.y; f[6]=v1.z; f[7]=v1.w;
    } else {
        int r0 = idx >> 7;                 // [0, 2048)
        int b_ = r0 >> 8, sloc = r0 & 255;
        r = b_ * 512 + ph * 256 + sloc;
        const float* s0 = (const float*)g_ctx  + (size_t)r * 1024 + c0;
        const float* s1 = (const float*)g_ctx2 + (size_t)r * 1024 + c0;
        float4 a0 = *(const float4*)(s0), a1 = *(const float4*)(s0 + 4);
        float4 b0 = *(const float4*)(s1), b1 = *(const float4*)(s1 + 4);
        f[0]=a0.x+b0.x; f[1]=a0.y+b0.y; f[2]=a0.z+b0.z; f[3]=a0.w+b0.w;
        f[4]=a1.x+b1.x; f[5]=a1.y+b1.y; f[6]=a1.z+b1.z; f[7]=a1.w+b1.w;
    }
    __nv_bfloat16* dst = which ? g_Actx : g_A;
    uint4 H, L;
    uint32_t hu[4], lu[4];
#pragma unroll
    for (int i = 0; i < 4; i++) {
        __nv_bfloat16 h0 = __float2bfloat16(f[2*i]);
        __nv_bfloat16 h1 = __float2bfloat16(f[2*i+1]);
        __nv_bfloat16 l0 = __float2bfloat16(f[2*i]   - __bfloat162float(h0));
        __nv_bfloat16 l1 = __float2bfloat16(f[2*i+1] - __bfloat162float(h1));
        hu[i] = pk2(h0, h1); lu[i] = pk2(l0, l1);
    }
    H.x = hu[0]; H.y = hu[1]; H.z = hu[2]; H.w = hu[3];
    L.x = lu[0]; L.y = lu[1]; L.z = lu[2]; L.w = lu[3];
    __nv_bfloat16* row = dst + (size_t)r * 3072;
    *(uint4*)(row + c0)        = H;
    *(uint4*)(row + 1024 + c0) = H;
    *(uint4*)(row + 2048 + c0) = L;
}

// ===========================================================================
// Weight split+transpose (4 weights, one launch): W[1024k,1024n]->B'[n][3072]
// ===========================================================================
__global__ __launch_bounds__(256) void k_wsplit(
    const float* __restrict__ W0, const float* __restrict__ W1,
    const float* __restrict__ W2, const float* __restrict__ W3)
{
    const int slot = blockIdx.z;
    const float* W = (slot == 0) ? W0 : (slot == 1) ? W1 : (slot == 2) ? W2 : W3;
    __nv_bfloat16* dst = (slot < 3) ? (g_Bqkv + (size_t)slot * 1024 * 3072) : g_Bo;
    int nl = blockIdx.x * 256 + threadIdx.x;
    int k0 = blockIdx.y << 3;
    uint4 H, L;
    uint32_t hu[4], lu[4];
#pragma unroll
    for (int i = 0; i < 4; i++) {
        float f0 = W[(size_t)(k0 + 2*i)     * 1024 + nl];
        float f1 = W[(size_t)(k0 + 2*i + 1) * 1024 + nl];
        __nv_bfloat16 h0 = __float2bfloat16(f0);
        __nv_bfloat16 h1 = __float2bfloat16(f1);
        __nv_bfloat16 l0 = __float2bfloat16(f0 - __bfloat162float(h0));
        __nv_bfloat16 l1 = __float2bfloat16(f1 - __bfloat162float(h1));
        hu[i] = pk2(h0, h1); lu[i] = pk2(l0, l1);
    }
    H.x = hu[0]; H.y = hu[1]; H.z = hu[2]; H.w = hu[3];
    L.x = lu[0]; L.y = lu[1]; L.z = lu[2]; L.w = lu[3];
    __nv_bfloat16* row = dst + (size_t)nl * 3072;
    *(uint4*)(row + k0)        = H;
    *(uint4*)(row + 1024 + k0) = L;
    *(uint4*)(row + 2048 + k0) = H;
}

// ===========================================================================
// EK split: fp32 [i,j,64] -> ekh/ekl bf16 (elementwise)
// ===========================================================================
__global__ __launch_bounds__(256) void k_split_ek(const float* __restrict__ EK)
{
    size_t base = ((size_t)blockIdx.x * 256 + threadIdx.x) * 8;
    float4 v0 = *(const float4*)(EK + base);
    float4 v1 = *(const float4*)(EK + base + 4);
    float f[8] = {v0.x, v0.y, v0.z, v0.w, v1.x, v1.y, v1.z, v1.w};
    uint4 H, L;
    uint32_t hu[4], lu[4];
#pragma unroll
    for (int i = 0; i < 4; i++) {
        __nv_bfloat16 h0 = __float2bfloat16(f[2*i]);
        __nv_bfloat16 h1 = __float2bfloat16(f[2*i+1]);
        __nv_bfloat16 l0 = __float2bfloat16(f[2*i]   - __bfloat162float(h0));
        __nv_bfloat16 l1 = __float2bfloat16(f[2*i+1] - __bfloat162float(h1));
        hu[i] = pk2(h0, h1); lu[i] = pk2(l0, l1);
    }
    H.x = hu[0]; H.y = hu[1]; H.z = hu[2]; H.w = hu[3];
    L.x = lu[0]; L.y = lu[1]; L.z = lu[2]; L.w = lu[3];
    *(uint4*)(ekh + base) = H;
    *(uint4*)(ekl + base) = L;
}

// ===========================================================================
// EV transpose-split: fp32 [i,j,64] -> evth/evtl bf16 [i,64,512]
// ===========================================================================
__global__ __launch_bounds__(256) void k_split_evt(const float* __restrict__ EV)
{
    __shared__ float ts[32][33];
    const int jt = blockIdx.x, dt = blockIdx.y, i = blockIdx.z;
    const int t = threadIdx.x;
    const int r = t >> 3, c0 = (t & 7) << 2;

    float4 v = *(const float4*)(EV + ((size_t)(i * SS_ + jt * 32 + r)) * DKV + dt * 32 + c0);
    ts[r][c0 + 0] = v.x; ts[r][c0 + 1] = v.y;
    ts[r][c0 + 2] = v.z; ts[r][c0 + 3] = v.w;
    __syncthreads();

    uint32_t hu[2], lu[2];
#pragma unroll
    for (int p = 0; p < 2; p++) {
        float f0 = ts[c0 + 2*p][r];
        float f1 = ts[c0 + 2*p + 1][r];
        __nv_bfloat16 h0 = __float2bfloat16(f0);
        __nv_bfloat16 h1 = __float2bfloat16(f1);
        __nv_bfloat16 l0 = __float2bfloat16(f0 - __bfloat162float(h0));
        __nv_bfloat16 l1 = __float2bfloat16(f1 - __bfloat162float(h1));
        hu[p] = pk2(h0, h1); lu[p] = pk2(l0, l1);
    }
    size_t off = ((size_t)i * DKV + dt * 32 + r) * SS_ + jt * 32 + c0;
    *(uint2*)(evth + off) = make_uint2(hu[0], hu[1]);
    *(uint2*)(evtl + off) = make_uint2(lu[0], lu[1]);
}

// ===========================================================================
// bf16 mma.sync GEMM (projections), 2-stage cp.async.
// mode 0: QKV, grid (24,32), m0 = blockIdx.y*128
// mode 1: OUT, grid (8,16), m0 = (by>>1)*512 + ph*256 + (by&1)*128
// ===========================================================================
#define KTOT   3072
#define NCHUNK 96

__global__ __launch_bounds__(256) void k_gemm_bf16(
    const float* __restrict__ b0p, const float* __restrict__ b1p,
    const float* __restrict__ b2p, float* __restrict__ outp, int mode, int ph)
{
    __shared__ __align__(16) char smem[2 * 2 * TILEB];

    const int tid  = threadIdx.x;
    const int wid  = tid >> 5, lane = tid & 31;
    const int wm   = wid >> 2, wn = wid & 3;
    const int n0   = blockIdx.x * 128;
    const int m0   = mode ? (int)((blockIdx.y >> 1) * 512 + ph * 256 + (blockIdx.y & 1) * 128)
                          : (int)(blockIdx.y * 128);
    const uint32_t sbase = s2u(smem);

    const __nv_bfloat16* __restrict__ Ag = mode ? g_Actx : g_A;
    const __nv_bfloat16* __restrict__ Bg = mode ? g_Bo   : g_Bqkv;

    const int lrow0 = tid >> 2;
    const int lseg  = (tid & 3) << 3;

    float acc[4][4][4];
#pragma unroll
    for (int i = 0; i < 4; i++)
#pragma unroll
        for (int j = 0; j < 4; j++)
#pragma unroll
            for (int q = 0; q < 4; q++) acc[i][j][q] = 0.f;

    {
        uint32_t dA = sbase, dB = sbase + TILEB;
#pragma unroll
        for (int u = 0; u < 2; u++) {
            int row = lrow0 + u * 64;
            CP_ASYNC16(dA + (row * LDS_ + lseg) * 2, Ag + (size_t)(m0 + row) * KTOT + lseg);
            CP_ASYNC16(dB + (row * LDS_ + lseg) * 2, Bg + (size_t)(n0 + row) * KTOT + lseg);
        }
        CP_COMMIT();
    }

    for (int c = 0; c < NCHUNK; c++) {
        CP_WAIT0();
        __syncthreads();

        if (c + 1 < NCHUNK) {
            uint32_t dA = sbase + ((c + 1) & 1) * 2 * TILEB;
            uint32_t dB = dA + TILEB;
            const int koff = (c + 1) * 32 + lseg;
#pragma unroll
            for (int u = 0; u < 2; u++) {
                int row = lrow0 + u * 64;
                CP_ASYNC16(dA + (row * LDS_ + lseg) * 2, Ag + (size_t)(m0 + row) * KTOT + koff);
                CP_ASYNC16(dB + (row * LDS_ + lseg) * 2, Bg + (size_t)(n0 + row) * KTOT + koff);
            }
            CP_COMMIT();
        }

        const uint32_t bufA = sbase + (c & 1) * 2 * TILEB;
        const uint32_t bufB = bufA + TILEB;
        const int lr = lane & 15, lc = (lane >> 4) << 3;

#pragma unroll
        for (int ks = 0; ks < 2; ks++) {
            uint32_t a[4][4];
#pragma unroll
            for (int mi = 0; mi < 4; mi++) {
                uint32_t addr = bufA + ((wm * 64 + mi * 16 + lr) * LDS_ + ks * 16 + lc) * 2;
                LDMATX4(a[mi][0], a[mi][1], a[mi][2], a[mi][3], addr);
            }
            uint32_t b[4][2];
#pragma unroll
            for (int ni2 = 0; ni2 < 2; ni2++) {
                uint32_t r0, r1, r2, r3;
                uint32_t addr = bufB + ((wn * 32 + ni2 * 16 + lr) * LDS_ + ks * 16 + lc) * 2;
                LDMATX4(r0, r1, r2, r3, addr);
                b[2 * ni2][0] = r0;     b[2 * ni2][1] = r2;
                b[2 * ni2 + 1][0] = r1; b[2 * ni2 + 1][1] = r3;
            }
#pragma unroll
            for (int mi = 0; mi < 4; mi++)
#pragma unroll
                for (int ni = 0; ni < 4; ni++)
                    MMA16816(acc[mi][ni], a[mi], b[ni]);
        }
        __syncthreads();
    }

    // -------- epilogue --------
    const int g  = lane >> 2;
    const int tc = (lane & 3) << 1;

    if (mode == 0) {
        const int proj = n0 >> 10;
        const float* bias = (proj == 0) ? b0p : (proj == 1) ? b1p : b2p;
#pragma unroll
        for (int mi = 0; mi < 4; mi++) {
            int m = m0 + wm * 64 + mi * 16 + g;
            int b_ = m >> 9, s_ = m & 511;
            int s2 = s_ + 8;
#pragma unroll
            for (int ni = 0; ni < 4; ni++) {
                int nl = (n0 & 1023) + wn * 32 + ni * 8 + tc;
                int hd = nl >> 6, d = nl & 63;
                int bh_ = b_ * HH + hd;
                float x0 = acc[mi][ni][0] + bias[nl];
                float x1 = acc[mi][ni][1] + bias[nl + 1];
                float x2 = acc[mi][ni][2] + bias[nl];
                float x3 = acc[mi][ni][3] + bias[nl + 1];
                __nv_bfloat16 hb0 = __float2bfloat16(x0), lb0 = __float2bfloat16(x0 - __bfloat162float(hb0));
                __nv_bfloat16 hb1 = __float2bfloat16(x1), lb1 = __float2bfloat16(x1 - __bfloat162float(hb1));
                __nv_bfloat16 hb2 = __float2bfloat16(x2), lb2 = __float2bfloat16(x2 - __bfloat162float(hb2));
                __nv_bfloat16 hb3 = __float2bfloat16(x3), lb3 = __float2bfloat16(x3 - __bfloat162float(hb3));
                if (proj < 2) {
                    __nv_bfloat16* ah = (proj == 0) ? qh : kh;
                    __nv_bfloat16* al = (proj == 0) ? ql : kl;
                    size_t o0 = ((size_t)bh_ * SS_ + s_) * DKV + d;
                    size_t o1 = o0 + 8 * DKV;
                    *(uint32_t*)(ah + o0) = pk2(hb0, hb1);
                    *(uint32_t*)(al + o0) = pk2(lb0, lb1);
                    *(uint32_t*)(ah + o1) = pk2(hb2, hb3);
                    *(uint32_t*)(al + o1) = pk2(lb2, lb3);
                } else {
                    size_t o = (size_t)bh_ * DKV * SS_ + (size_t)d * SS_;
                    vth[o + s_]       = hb0;  vtl[o + s_]       = lb0;
                    vth[o + SS_ + s_] = hb1;  vtl[o + SS_ + s_] = lb1;
                    vth[o + s2]       = hb2;  vtl[o + s2]       = lb2;
                    vth[o + SS_ + s2] = hb3;  vtl[o + SS_ + s2] = lb3;
                }
            }
        }
    } else {
#pragma unroll
        for (int mi = 0; mi < 4; mi++) {
            int m = m0 + wm * 64 + mi * 16 + g;
#pragma unroll
            for (int ni = 0; ni < 4; ni++) {
                int ncol = n0 + wn * 32 + ni * 8 + tc;
                float2 o0 = {acc[mi][ni][0] + b0p[ncol],
                             acc[mi][ni][1] + b0p[ncol + 1]};
                float2 o1 = {acc[mi][ni][2] + b0p[ncol],
                             acc[mi][ni][3] + b0p[ncol + 1]};
                *(float2*)(outp + (size_t)m * DM + ncol) = o0;
                *(float2*)(outp + (size_t)(m + 8) * DM + ncol) = o1;
            }
        }
    }
}

// ===========================================================================
// Scores GEMM (3-term bf16), phased by i.
// mode 0 (content): grid(4 jt, 2 it, 128 bh), i0 = (blockIdx.y+ofs)*128
// mode 1 (edge):    grid(4 jt, 256 i),        iE = blockIdx.y + ofs
// ===========================================================================
__global__ __launch_bounds__(256) void k_scores(const float* __restrict__ bias,
                                                int mode, int ofs)
{
    __shared__ __align__(16) char smem[2 * 2 * TILEB];
    const int tid = threadIdx.x, wid = tid >> 5, lane = tid & 31;
    const int wm = wid >> 2, wn = wid & 3;
    const int j0 = blockIdx.x * 128;

    const __nv_bfloat16 *A0, *A1, *B0, *B1;
    size_t rsA;
    int i0 = 0, bh = 0, iE = 0;
    if (mode == 0) {
        i0 = (blockIdx.y + ofs) * 128; bh = blockIdx.z;
        A0 = qh + ((size_t)bh * SS_ + i0) * DKV;
        A1 = ql + ((size_t)bh * SS_ + i0) * DKV;
        B0 = kh + ((size_t)bh * SS_ + j0) * DKV;
        B1 = kl + ((size_t)bh * SS_ + j0) * DKV;
        rsA = DKV;
    } else {
        iE = blockIdx.y + ofs;
        A0 = qh + (size_t)iE * DKV;
        A1 = ql + (size_t)iE * DKV;
        B0 = ekh + ((size_t)iE * SS_ + j0) * DKV;
        B1 = ekl + ((size_t)iE * SS_ + j0) * DKV;
        rsA = (size_t)SS_ * DKV;
    }
    const __nv_bfloat16* At[3] = {A0, A0, A1};
    const __nv_bfloat16* Bt[3] = {B0, B1, B0};

    const uint32_t sbase = s2u(smem);
    const int lrow0 = tid >> 2, lseg = (tid & 3) << 3;

    float acc[4][4][4];
#pragma unroll
    for (int i = 0; i < 4; i++)
#pragma unroll
        for (int j = 0; j < 4; j++)
#pragma unroll
            for (int q = 0; q < 4; q++) acc[i][j][q] = 0.f;

    {
        uint32_t dA = sbase, dB = sbase + TILEB;
#pragma unroll
        for (int u = 0; u < 2; u++) {
            int row = lrow0 + u * 64;
            CP_ASYNC16(dA + (row * LDS_ + lseg) * 2, At[0] + (size_t)row * rsA + lseg);
            CP_ASYNC16(dB + (row * LDS_ + lseg) * 2, Bt[0] + (size_t)row * DKV + lseg);
        }
        CP_COMMIT();
    }

    for (int c = 0; c < 6; c++) {
        CP_WAIT0();
        __syncthreads();

        if (c + 1 < 6) {
            int t2 = (c + 1) >> 1, ko2 = ((c + 1) & 1) * 32;
            uint32_t dA = sbase + ((c + 1) & 1) * 2 * TILEB;
            uint32_t dB = dA + TILEB;
#pragma unroll
            for (int u = 0; u < 2; u++) {
                int row = lrow0 + u * 64;
                CP_ASYNC16(dA + (row * LDS_ + lseg) * 2, At[t2] + (size_t)row * rsA + ko2 + lseg);
                CP_ASYNC16(dB + (row * LDS_ + lseg) * 2, Bt[t2] + (size_t)row * DKV + ko2 + lseg);
            }
            CP_COMMIT();
        }

        const uint32_t bufA = sbase + (c & 1) * 2 * TILEB;
        const uint32_t bufB = bufA + TILEB;
        const int lr = lane & 15, lc = (lane >> 4) << 3;

#pragma unroll
        for (int ks = 0; ks < 2; ks++) {
            uint32_t a[4][4];
#pragma unroll
            for (int mi = 0; mi < 4; mi++) {
                uint32_t addr = bufA + ((wm * 64 + mi * 16 + lr) * LDS_ + ks * 16 + lc) * 2;
                LDMATX4(a[mi][0], a[mi][1], a[mi][2], a[mi][3], addr);
            }
            uint32_t b[4][2];
#pragma unroll
            for (int ni2 = 0; ni2 < 2; ni2++) {
                uint32_t r0, r1, r2, r3;
                uint32_t addr = bufB + ((wn * 32 + ni2 * 16 + lr) * LDS_ + ks * 16 + lc) * 2;
                LDMATX4(r0, r1, r2, r3, addr);
                b[2 * ni2][0] = r0;     b[2 * ni2][1] = r2;
                b[2 * ni2 + 1][0] = r1; b[2 * ni2 + 1][1] = r3;
            }
#pragma unroll
            for (int mi = 0; mi < 4; mi++)
#pragma unroll
                for (int ni = 0; ni < 4; ni++)
                    MMA16816(acc[mi][ni], a[mi], b[ni]);
        }
        __syncthreads();
    }

    const int g = lane >> 2, tc = (lane & 3) << 1;
#pragma unroll
    for (int mi = 0; mi < 4; mi++) {
        int m = wm * 64 + mi * 16 + g;
#pragma unroll
        for (int ni = 0; ni < 4; ni++) {
            int jc = j0 + wn * 32 + ni * 8 + tc;
            if (mode == 0) {
                size_t base0 = ((size_t)bh * SS_ + (i0 + m)) * SS_ + jc;
                size_t base1 = base0 + 8 * SS_;
                float2 o0 = {acc[mi][ni][0] * SCALE + bias[base0],
                             acc[mi][ni][1] * SCALE + bias[base0 + 1]};
                float2 o1 = {acc[mi][ni][2] * SCALE + bias[base1],
                             acc[mi][ni][3] * SCALE + bias[base1 + 1]};
                *(float2*)(g_sc + base0) = o0;
                *(float2*)(g_sc + base1) = o1;
            } else {
                size_t base0 = ((size_t)m * SS_ + iE) * SS_ + jc;
                size_t base1 = base0 + (size_t)8 * SS_ * SS_;
                float2 o0 = {acc[mi][ni][0] * SCALE, acc[mi][ni][1] * SCALE};
                float2 o1 = {acc[mi][ni][2] * SCALE, acc[mi][ni][3] * SCALE};
                *(float2*)(g_sc2 + base0) = o0;
                *(float2*)(g_sc2 + base1) = o1;
            }
        }
    }
}

// ===========================================================================
// Softmax + split, phased by i: grid 4096 (8 warps = 8 rows/blk)
// idx -> bh = idx>>8, i = i_ofs + (idx & 255)
// ===========================================================================
__global__ __launch_bounds__(256) void k_softmax_split(int i_ofs)
{
    const int warp = threadIdx.x >> 5, lane = threadIdx.x & 31;
    const int idx = blockIdx.x * 8 + warp;
    const int bh = idx >> 8, ii = i_ofs + (idx & 255);
    const size_t row = (size_t)bh * SS_ + ii;
    const float* p  = g_sc  + row * SS_;
    const float* p2 = g_sc2 + row * SS_;

    float4 v[4];
    float mx = -1e30f;
#pragma unroll
    for (int w = 0; w < 4; w++) {
        float4 a = *(const float4*)(p  + w * 128 + lane * 4);
        float4 b = *(const float4*)(p2 + w * 128 + lane * 4);
        v[w].x = a.x + b.x; v[w].y = a.y + b.y;
        v[w].z = a.z + b.z; v[w].w = a.w + b.w;
        mx = fmaxf(mx, fmaxf(fmaxf(v[w].x, v[w].y), fmaxf(v[w].z, v[w].w)));
    }
#pragma unroll
    for (int o = 16; o > 0; o >>= 1) mx = fmaxf(mx, __shfl_xor_sync(~0u, mx, o));

    float sum = 0.f;
#pragma unroll
    for (int w = 0; w < 4; w++) {
        v[w].x = __expf(v[w].x - mx); v[w].y = __expf(v[w].y - mx);
        v[w].z = __expf(v[w].z - mx); v[w].w = __expf(v[w].w - mx);
        sum += v[w].x + v[w].y + v[w].z + v[w].w;
    }
#pragma unroll
    for (int o = 16; o > 0; o >>= 1) sum += __shfl_xor_sync(~0u, sum, o);
    float r = 1.f / sum;
#pragma unroll
    for (int w = 0; w < 4; w++) {
        float f[4] = {v[w].x * r, v[w].y * r, v[w].z * r, v[w].w * r};
        uint32_t hu[2], lu[2];
#pragma unroll
        for (int pq = 0; pq < 2; pq++) {
            __nv_bfloat16 h0 = __float2bfloat16(f[2*pq]);
            __nv_bfloat16 h1 = __float2bfloat16(f[2*pq+1]);
            __nv_bfloat16 l0 = __float2bfloat16(f[2*pq]   - __bfloat162float(h0));
            __nv_bfloat16 l1 = __float2bfloat16(f[2*pq+1] - __bfloat162float(h1));
            hu[pq] = pk2(h0, h1); lu[pq] = pk2(l0, l1);
        }
        size_t off = row * SS_ + w * 128 + lane * 4;
        *(uint2*)(wh + off) = make_uint2(hu[0], hu[1]);
        *(uint2*)(wl + off) = make_uint2(lu[0], lu[1]);
    }
}

// ===========================================================================
// Context GEMM (3-term bf16), phased by i.
// mode 0 (content): grid(2 it, 128 bh), i0 = (blockIdx.x+ofs)*128 -> g_ctx
// mode 1 (edge):    grid(256 i),        iE = blockIdx.x + ofs     -> g_ctx2
// ===========================================================================
#define CT_A_TILEB (128 * LDS_ * 2)
#define CT_B_TILEB (64 * LDS_ * 2)
#define CT_STAGE   (CT_A_TILEB + CT_B_TILEB)

__global__ __launch_bounds__(256) void k_ctx(int mode, int ofs)
{
    __shared__ __align__(16) char smem[2 * CT_STAGE];
    const int tid = threadIdx.x, wid = tid >> 5, lane = tid & 31;
    const int wm = wid >> 1, wn = wid & 1;

    const __nv_bfloat16 *A0, *A1, *B0, *B1;
    size_t rsA;
    int i0 = 0, bh = 0, iE = 0;
    if (mode == 0) {
        bh = blockIdx.y; i0 = (blockIdx.x + ofs) * 128;
        A0 = wh + (size_t)bh * SS_ * SS_ + (size_t)i0 * SS_;
        A1 = wl + (size_t)bh * SS_ * SS_ + (size_t)i0 * SS_;
        B0 = vth + (size_t)bh * DKV * SS_;
        B1 = vtl + (size_t)bh * DKV * SS_;
        rsA = SS_;
    } else {
        iE = blockIdx.x + ofs;
        A0 = wh + (size_t)iE * SS_;
        A1 = wl + (size_t)iE * SS_;
        B0 = evth + (size_t)iE * DKV * SS_;
        B1 = evtl + (size_t)iE * DKV * SS_;
        rsA = (size_t)SS_ * SS_;
    }
    const __nv_bfloat16* At[3] = {A0, A0, A1};
    const __nv_bfloat16* Bt[3] = {B0, B1, B0};

    const uint32_t sbase = s2u(smem);
    const int arow = tid >> 1, aseg = (tid & 1) << 4;
    const int brow = tid >> 2, bseg = (tid & 3) << 3;

    float acc[2][4][4];
#pragma unroll
    for (int i = 0; i < 2; i++)
#pragma unroll
        for (int j = 0; j < 4; j++)
#pragma unroll
            for (int q = 0; q < 4; q++) acc[i][j][q] = 0.f;

    {
        uint32_t dA = sbase, dB = sbase + CT_A_TILEB;
        CP_ASYNC16(dA + (arow * LDS_ + aseg) * 2,     At[0] + (size_t)arow * rsA + aseg);
        CP_ASYNC16(dA + (arow * LDS_ + aseg + 8) * 2, At[0] + (size_t)arow * rsA + aseg + 8);
        CP_ASYNC16(dB + (brow * LDS_ + bseg) * 2,     Bt[0] + (size_t)brow * SS_ + bseg);
        CP_COMMIT();
    }

    for (int c = 0; c < 48; c++) {
        CP_WAIT0();
        __syncthreads();

        if (c + 1 < 48) {
            int t2 = (c + 1) >> 4, ko2 = ((c + 1) & 15) * 32;
            uint32_t dA = sbase + ((c + 1) & 1) * CT_STAGE;
            uint32_t dB = dA + CT_A_TILEB;
            CP_ASYNC16(dA + (arow * LDS_ + aseg) * 2,     At[t2] + (size_t)arow * rsA + ko2 + aseg);
            CP_ASYNC16(dA + (arow * LDS_ + aseg + 8) * 2, At[t2] + (size_t)arow * rsA + ko2 + aseg + 8);
            CP_ASYNC16(dB + (brow * LDS_ + bseg) * 2,     Bt[t2] + (size_t)brow * SS_ + ko2 + bseg);
            CP_COMMIT();
        }

        const uint32_t bufA = sbase + (c & 1) * CT_STAGE;
        const uint32_t bufB = bufA + CT_A_TILEB;
        const int lr = lane & 15, lc = (lane >> 4) << 3;

#pragma unroll
        for (int ks = 0; ks < 2; ks++) {
            uint32_t a[2][4];
#pragma unroll
            for (int mi = 0; mi < 2; mi++) {
                uint32_t addr = bufA + ((wm * 32 + mi * 16 + lr) * LDS_ + ks * 16 + lc) * 2;
                LDMATX4(a[mi][0], a[mi][1], a[mi][2], a[mi][3], addr);
            }
            uint32_t b[4][2];
#pragma unroll
            for (int ni2 = 0; ni2 < 2; ni2++) {
                uint32_t r0, r1, r2, r3;
                uint32_t addr = bufB + ((wn * 32 + ni2 * 16 + lr) * LDS_ + ks * 16 + lc) * 2;
                LDMATX4(r0, r1, r2, r3, addr);
                b[2 * ni2][0] = r0;     b[2 * ni2][1] = r2;
                b[2 * ni2 + 1][0] = r1; b[2 * ni2 + 1][1] = r3;
            }
#pragma unroll
            for (int mi = 0; mi < 2; mi++)
#pragma unroll
                for (int ni = 0; ni < 4; ni++)
                    MMA16816(acc[mi][ni], a[mi], b[ni]);
        }
        __syncthreads();
    }

    const int g = lane >> 2, tc = (lane & 3) << 1;
#pragma unroll
    for (int mi = 0; mi < 2; mi++) {
        int m = wm * 32 + mi * 16 + g;
#pragma unroll
        for (int ni = 0; ni < 4; ni++) {
            int ncol = wn * 32 + ni * 8 + tc;
            if (mode == 0) {
                int i = i0 + m;
                size_t a0 = ((size_t)(bh >> 4) * SS_ + i) * DM + (bh & 15) * DKV + ncol;
                size_t a1 = a0 + (size_t)8 * DM;
                *(float2*)(g_ctx + a0) = make_float2(acc[mi][ni][0], acc[mi][ni][1]);
                *(float2*)(g_ctx + a1) = make_float2(acc[mi][ni][2], acc[mi][ni][3]);
            } else {
                int bh0 = m, bh1 = m + 8;
                size_t a0 = ((size_t)(bh0 >> 4) * SS_ + iE) * DM + (bh0 & 15) * DKV + ncol;
                size_t a1 = ((size_t)(bh1 >> 4) * SS_ + iE) * DM + (bh1 & 15) * DKV + ncol;
                *(float2*)(g_ctx2 + a0) = make_float2(acc[mi][ni][0], acc[mi][ni][1]);
                *(float2*)(g_ctx2 + a1) = make_float2(acc[mi][ni][2], acc[mi][ni][3]);
            }
        }
    }
}

// ===========================================================================
// Launcher — 3 streams, two i-phases, ALL side branches joined into origin.
// ===========================================================================
extern "C" void kernel_launch(void* const* d_in, const int* in_sizes, int n_in,
                              void* d_out, int out_size)
{
    const float* queries     = (const float*)d_in[0];
    const float* edges_key   = (const float*)d_in[1];
    const float* edges_value = (const float*)d_in[2];
    const float* attn_bias   = (const float*)d_in[3];
    const float* Wq = (const float*)d_in[4];
    const float* bq = (const float*)d_in[5];
    const float* Wk = (const float*)d_in[6];
    const float* bk = (const float*)d_in[7];
    const float* Wv = (const float*)d_in[8];
    const float* bv = (const float*)d_in[9];
    const float* Wo = (const float*)d_in[10];
    const float* bo = (const float*)d_in[11];
    float* out = (float*)d_out;

    static cudaStream_t s2 = nullptr, s3 = nullptr;
    static cudaEvent_t evFork = nullptr, evEdgeSplit = nullptr, evQKV = nullptr,
                       evCS0 = nullptr,
                       evES0 = nullptr, evES1 = nullptr,
                       evSM0 = nullptr, evSM1 = nullptr,
                       evCtxE0 = nullptr, evCtxE1 = nullptr,
                       evOut0 = nullptr;
    if (!s2) {
        cudaStreamCreateWithFlags(&s2, cudaStreamNonBlocking);
        cudaStreamCreateWithFlags(&s3, cudaStreamNonBlocking);
        cudaEventCreateWithFlags(&evFork,      cudaEventDisableTiming);
        cudaEventCreateWithFlags(&evEdgeSplit, cudaEventDisableTiming);
        cudaEventCreateWithFlags(&evQKV,       cudaEventDisableTiming);
        cudaEventCreateWithFlags(&evCS0,       cudaEventDisableTiming);
        cudaEventCreateWithFlags(&evES0,       cudaEventDisableTiming);
        cudaEventCreateWithFlags(&evES1,       cudaEventDisableTiming);
        cudaEventCreateWithFlags(&evSM0,       cudaEventDisableTiming);
        cudaEventCreateWithFlags(&evSM1,       cudaEventDisableTiming);
        cudaEventCreateWithFlags(&evCtxE0,     cudaEventDisableTiming);
        cudaEventCreateWithFlags(&evCtxE1,     cudaEventDisableTiming);
        cudaEventCreateWithFlags(&evOut0,      cudaEventDisableTiming);
    }

    cudaStream_t st = 0;
    cudaStreamCaptureStatus cs = cudaStreamCaptureStatusNone;
    if (cudaStreamIsCapturing(cudaStreamPerThread, &cs) == cudaSuccess &&
        cs == cudaStreamCaptureStatusActive)
        st = cudaStreamPerThread;

    // ---- fork: edge-tensor splits overlap the projection path (s2)
    cudaEventRecord(evFork, st);
    cudaStreamWaitEvent(s2, evFork, 0);
    k_split_ek <<<8192, 256, 0, s2>>>(edges_key);
    k_split_evt<<<dim3(16, 2, 512), 256, 0, s2>>>(edges_value);
    cudaEventRecord(evEdgeSplit, s2);

    // ---- projection path (st)
    k_split <<<2048, 256, 0, st>>>(queries, 0, 0);
    k_wsplit<<<dim3(4, 128, 4), 256, 0, st>>>(Wq, Wk, Wv, Wo);
    k_gemm_bf16<<<dim3(24, 32), 256, 0, st>>>(bq, bk, bv, nullptr, 0, 0);
    cudaEventRecord(evQKV, st);

    // ---- edge scores, two phases (s3)
    cudaStreamWaitEvent(s3, evQKV, 0);
    cudaStreamWaitEvent(s3, evEdgeSplit, 0);
    k_scores<<<dim3(4, 256), 256, 0, s3>>>(nullptr, 1, 0);
    cudaEventRecord(evES0, s3);
    k_scores<<<dim3(4, 256), 256, 0, s3>>>(nullptr, 1, 256);
    cudaEventRecord(evES1, s3);

    // ---- content scores, two phases (st)
    k_scores<<<dim3(4, 2, 128), 256, 0, st>>>(attn_bias, 0, 0);
    cudaEventRecord(evCS0, st);
    k_scores<<<dim3(4, 2, 128), 256, 0, st>>>(attn_bias, 0, 2);

    // ---- softmax phase 0 (s2): overlaps scores phase 1
    cudaStreamWaitEvent(s2, evCS0, 0);
    cudaStreamWaitEvent(s2, evES0, 0);
    k_softmax_split<<<4096, 256, 0, s2>>>(0);
    cudaEventRecord(evSM0, s2);

    // ---- softmax phase 1 (st)
    cudaStreamWaitEvent(st, evES1, 0);
    k_softmax_split<<<4096, 256, 0, st>>>(256);
    cudaEventRecord(evSM1, st);

    // ---- edge context phases (s3)
    cudaStreamWaitEvent(s3, evSM0, 0);
    k_ctx<<<dim3(256), 256, 0, s3>>>(1, 0);
    cudaEventRecord(evCtxE0, s3);
    cudaStreamWaitEvent(s3, evSM1, 0);
    k_ctx<<<dim3(256), 256, 0, s3>>>(1, 256);
    cudaEventRecord(evCtxE1, s3);

    // ---- content context phase 0 + OUT phase 0 (s2; after evSM0 by FIFO)
    k_ctx<<<dim3(2, 128), 256, 0, s2>>>(0, 0);
    cudaStreamWaitEvent(s2, evCtxE0, 0);
    k_split<<<1024, 256, 0, s2>>>(nullptr, 1, 0);
    k_gemm_bf16<<<dim3(8, 16), 256, 0, s2>>>(bo, nullptr, nullptr, out, 1, 0);
    cudaEventRecord(evOut0, s2);

    // ---- content context phase 1 + OUT phase 1 (st; after evSM1 by FIFO)
    k_ctx<<<dim3(2, 128), 256, 0, st>>>(0, 2);
    cudaStreamWaitEvent(st, evCtxE1, 0);
    k_split<<<1024, 256, 0, st>>>(nullptr, 1, 1);
    cudaStreamWaitEvent(st, evOut0, 0);   // join s2's terminal branch
    k_gemm_bf16<<<dim3(8, 16), 256, 0, st>>>(bo, nullptr, nullptr, out, 1, 1);
}

// round 10
// speedup vs baseline: 1.1897x; 1.1897x over previous
#include <cuda_runtime.h>
#include <cuda_bf16.h>
#include <cuda_fp16.h>
#include <cstdint>

// ---------------------------------------------------------------------------
// Problem constants: B=8, S=512, D_MODEL=1024, H=16, DK=DV=64, BH=128
// ---------------------------------------------------------------------------
#define BB   8
#define SS_  512
#define DM   1024
#define HH   16
#define DKV  64
#define BH   128
#define SCALE 0.125f

// ---------------------------------------------------------------------------
// Scratch (device globals)
// ---------------------------------------------------------------------------
__device__ float g_sc  [(size_t)BH * SS_ * SS_];   // content scores + bias
__device__ float g_sc2 [(size_t)BH * SS_ * SS_];   // edge scores
__device__ float g_ctx [(size_t)BB * SS_ * DM];    // content context
__device__ float g_ctx2[(size_t)BB * SS_ * DM];    // edge context

// projection staging: A = [Xfh | Xfl] fp16 (exact to eps_fp16^2), B = Wf fp16
__device__ __align__(16) __half g_A   [(size_t)4096 * 2048];
__device__ __align__(16) __half g_Actx[(size_t)4096 * 2048];
__device__ __align__(16) __half g_Bqkv[(size_t)3072 * 1024];
__device__ __align__(16) __half g_Bo  [(size_t)1024 * 1024];

// attention operand splits (hi/lo bf16) — unchanged 3-term machinery
__device__ __align__(16) __nv_bfloat16 qh [(size_t)BH * SS_ * DKV];
__device__ __align__(16) __nv_bfloat16 ql [(size_t)BH * SS_ * DKV];
__device__ __align__(16) __nv_bfloat16 kh [(size_t)BH * SS_ * DKV];
__device__ __align__(16) __nv_bfloat16 kl [(size_t)BH * SS_ * DKV];
__device__ __align__(16) __nv_bfloat16 vth[(size_t)BH * DKV * SS_];  // [bh,d,s]
__device__ __align__(16) __nv_bfloat16 vtl[(size_t)BH * DKV * SS_];
__device__ __align__(16) __nv_bfloat16 ekh [(size_t)SS_ * SS_ * DKV]; // [i,j,d]
__device__ __align__(16) __nv_bfloat16 ekl [(size_t)SS_ * SS_ * DKV];
__device__ __align__(16) __nv_bfloat16 evth[(size_t)SS_ * DKV * SS_]; // [i,d,j]
__device__ __align__(16) __nv_bfloat16 evtl[(size_t)SS_ * DKV * SS_];
__device__ __align__(16) __nv_bfloat16 wh [(size_t)BH * SS_ * SS_];   // [bh,i,j]
__device__ __align__(16) __nv_bfloat16 wl [(size_t)BH * SS_ * SS_];

__device__ __forceinline__ uint32_t s2u(const void* p) {
    uint32_t a;
    asm("{ .reg .u64 t; cvta.to.shared.u64 t, %1; cvt.u32.u64 %0, t; }"
        : "=r"(a) : "l"(p));
    return a;
}
__device__ __forceinline__ uint32_t pk2(__nv_bfloat16 a, __nv_bfloat16 b) {
    return (uint32_t)__bfloat16_as_ushort(a) | ((uint32_t)__bfloat16_as_ushort(b) << 16);
}
__device__ __forceinline__ uint32_t pk2h(__half a, __half b) {
    return (uint32_t)__half_as_ushort(a) | ((uint32_t)__half_as_ushort(b) << 16);
}

#define CP_ASYNC16(dst, src) \
    asm volatile("cp.async.cg.shared.global [%0], [%1], 16;" :: "r"(dst), "l"(src) : "memory")
#define CP_COMMIT() asm volatile("cp.async.commit_group;" ::: "memory")
#define CP_WAIT0()  asm volatile("cp.async.wait_group 0;" ::: "memory")

#define LDMATX4(r0, r1, r2, r3, addr) \
    asm volatile("ldmatrix.sync.aligned.m8n8.x4.shared.b16 {%0,%1,%2,%3}, [%4];" \
        : "=r"(r0), "=r"(r1), "=r"(r2), "=r"(r3) : "r"(addr))

#define MMA16816(c, a, b) \
    asm volatile("mma.sync.aligned.m16n8k16.row.col.f32.bf16.bf16.f32 " \
        "{%0,%1,%2,%3}, {%4,%5,%6,%7}, {%8,%9}, {%0,%1,%2,%3};" \
        : "+f"((c)[0]), "+f"((c)[1]), "+f"((c)[2]), "+f"((c)[3]) \
        : "r"((a)[0]), "r"((a)[1]), "r"((a)[2]), "r"((a)[3]), \
          "r"((b)[0]), "r"((b)[1]))

#define MMA16816H(c, a, b) \
    asm volatile("mma.sync.aligned.m16n8k16.row.col.f32.f16.f16.f32 " \
        "{%0,%1,%2,%3}, {%4,%5,%6,%7}, {%8,%9}, {%0,%1,%2,%3};" \
        : "+f"((c)[0]), "+f"((c)[1]), "+f"((c)[2]), "+f"((c)[3]) \
        : "r"((a)[0]), "r"((a)[1]), "r"((a)[2]), "r"((a)[3]), \
          "r"((b)[0]), "r"((b)[1]))

#define LDS_   40                 // padded row stride in 16-bit elems (80 bytes)
#define TILEB  (128 * LDS_ * 2)   // 10240 bytes

// ===========================================================================
// fp16 hi/lo split: fp32 [4096,1024] -> g_A / g_Actx [4096][Xfh(1024)|Xfl(1024)]
// which=0: src=queries -> g_A ; which=1: src=g_ctx+g_ctx2 -> g_Actx
// ===========================================================================
__global__ __launch_bounds__(256) void k_split(const float* __restrict__ src_in, int which)
{
    int idx = blockIdx.x * 256 + threadIdx.x;
    int r = idx >> 7;
    int c0 = (idx & 127) << 3;
    float f[8];
    if (which == 0) {
        const float* s = src_in + (size_t)r * 1024 + c0;
        float4 v0 = *(const float4*)(s);
        float4 v1 = *(const float4*)(s + 4);
        f[0]=v0.x; f[1]=v0.y; f[2]=v0.z; f[3]=v0.w;
        f[4]=v1.x; f[5]=v1.y; f[6]=v1.z; f[7]=v1.w;
    } else {
        const float* s0 = (const float*)g_ctx  + (size_t)r * 1024 + c0;
        const float* s1 = (const float*)g_ctx2 + (size_t)r * 1024 + c0;
        float4 a0 = *(const float4*)(s0), a1 = *(const float4*)(s0 + 4);
        float4 b0 = *(const float4*)(s1), b1 = *(const float4*)(s1 + 4);
        f[0]=a0.x+b0.x; f[1]=a0.y+b0.y; f[2]=a0.z+b0.z; f[3]=a0.w+b0.w;
        f[4]=a1.x+b1.x; f[5]=a1.y+b1.y; f[6]=a1.z+b1.z; f[7]=a1.w+b1.w;
    }
    __half* dst = which ? g_Actx : g_A;
    uint4 H, L;
    uint32_t hu[4], lu[4];
#pragma unroll
    for (int i = 0; i < 4; i++) {
        __half h0 = __float2half_rn(f[2*i]);
        __half h1 = __float2half_rn(f[2*i+1]);
        __half l0 = __float2half_rn(f[2*i]   - __half2float(h0));
        __half l1 = __float2half_rn(f[2*i+1] - __half2float(h1));
        hu[i] = pk2h(h0, h1); lu[i] = pk2h(l0, l1);
    }
    H.x = hu[0]; H.y = hu[1]; H.z = hu[2]; H.w = hu[3];
    L.x = lu[0]; L.y = lu[1]; L.z = lu[2]; L.w = lu[3];
    __half* row = dst + (size_t)r * 2048;
    *(uint4*)(row + c0)        = H;   // Xfh
    *(uint4*)(row + 1024 + c0) = L;   // Xfl
}

// ===========================================================================
// Weight fp16 transpose (4 weights): W[1024k,1024n] -> Bf[n][1024] fp16
// ===========================================================================
__global__ __launch_bounds__(256) void k_wsplit(
    const float* __restrict__ W0, const float* __restrict__ W1,
    const float* __restrict__ W2, const float* __restrict__ W3)
{
    const int slot = blockIdx.z;
    const float* W = (slot == 0) ? W0 : (slot == 1) ? W1 : (slot == 2) ? W2 : W3;
    __half* dst = (slot < 3) ? (g_Bqkv + (size_t)slot * 1024 * 1024) : g_Bo;
    int nl = blockIdx.x * 256 + threadIdx.x;
    int k0 = blockIdx.y << 3;
    uint32_t hu[4];
#pragma unroll
    for (int i = 0; i < 4; i++) {
        __half h0 = __float2half_rn(W[(size_t)(k0 + 2*i)     * 1024 + nl]);
        __half h1 = __float2half_rn(W[(size_t)(k0 + 2*i + 1) * 1024 + nl]);
        hu[i] = pk2h(h0, h1);
    }
    uint4 H; H.x = hu[0]; H.y = hu[1]; H.z = hu[2]; H.w = hu[3];
    *(uint4*)(dst + (size_t)nl * 1024 + k0) = H;
}

// ===========================================================================
// EK split: fp32 [i,j,64] -> ekh/ekl bf16 (elementwise)
// ===========================================================================
__global__ __launch_bounds__(256) void k_split_ek(const float* __restrict__ EK)
{
    size_t base = ((size_t)blockIdx.x * 256 + threadIdx.x) * 8;
    float4 v0 = *(const float4*)(EK + base);
    float4 v1 = *(const float4*)(EK + base + 4);
    float f[8] = {v0.x, v0.y, v0.z, v0.w, v1.x, v1.y, v1.z, v1.w};
    uint4 H, L;
    uint32_t hu[4], lu[4];
#pragma unroll
    for (int i = 0; i < 4; i++) {
        __nv_bfloat16 h0 = __float2bfloat16(f[2*i]);
        __nv_bfloat16 h1 = __float2bfloat16(f[2*i+1]);
        __nv_bfloat16 l0 = __float2bfloat16(f[2*i]   - __bfloat162float(h0));
        __nv_bfloat16 l1 = __float2bfloat16(f[2*i+1] - __bfloat162float(h1));
        hu[i] = pk2(h0, h1); lu[i] = pk2(l0, l1);
    }
    H.x = hu[0]; H.y = hu[1]; H.z = hu[2]; H.w = hu[3];
    L.x = lu[0]; L.y = lu[1]; L.z = lu[2]; L.w = lu[3];
    *(uint4*)(ekh + base) = H;
    *(uint4*)(ekl + base) = L;
}

// ===========================================================================
// EV transpose-split: fp32 [i,j,64] -> evth/evtl bf16 [i,64,512]
// ===========================================================================
__global__ __launch_bounds__(256) void k_split_evt(const float* __restrict__ EV)
{
    __shared__ float ts[32][33];
    const int jt = blockIdx.x, dt = blockIdx.y, i = blockIdx.z;
    const int t = threadIdx.x;
    const int r = t >> 3, c0 = (t & 7) << 2;

    float4 v = *(const float4*)(EV + ((size_t)(i * SS_ + jt * 32 + r)) * DKV + dt * 32 + c0);
    ts[r][c0 + 0] = v.x; ts[r][c0 + 1] = v.y;
    ts[r][c0 + 2] = v.z; ts[r][c0 + 3] = v.w;
    __syncthreads();

    uint32_t hu[2], lu[2];
#pragma unroll
    for (int p = 0; p < 2; p++) {
        float f0 = ts[c0 + 2*p][r];
        float f1 = ts[c0 + 2*p + 1][r];
        __nv_bfloat16 h0 = __float2bfloat16(f0);
        __nv_bfloat16 h1 = __float2bfloat16(f1);
        __nv_bfloat16 l0 = __float2bfloat16(f0 - __bfloat162float(h0));
        __nv_bfloat16 l1 = __float2bfloat16(f1 - __bfloat162float(h1));
        hu[p] = pk2(h0, h1); lu[p] = pk2(l0, l1);
    }
    size_t off = ((size_t)i * DKV + dt * 32 + r) * SS_ + jt * 32 + c0;
    *(uint2*)(evth + off) = make_uint2(hu[0], hu[1]);
    *(uint2*)(evtl + off) = make_uint2(lu[0], lu[1]);
}

// ===========================================================================
// fp16 mma.sync GEMM (projections): C[4096,N] = [Xfh|Xfl] @ [Wf;Wf]^T
// K=2048 on A side; B row is 1024 wide, K index masked (&1023) — second
// K-pass re-reads the same B from L2. 2-stage cp.async, 128x128 CTA.
// mode 0: QKV -> q/k splits + transposed-v splits; mode 1: OUT -> outp
// ===========================================================================
#define KTOT   2048
#define NCHUNK 64

__global__ __launch_bounds__(256) void k_gemm_f16(
    const float* __restrict__ b0p, const float* __restrict__ b1p,
    const float* __restrict__ b2p, float* __restrict__ outp, int mode)
{
    __shared__ __align__(16) char smem[2 * 2 * TILEB];

    const int tid  = threadIdx.x;
    const int wid  = tid >> 5, lane = tid & 31;
    const int wm   = wid >> 2, wn = wid & 3;
    const int m0   = blockIdx.y * 128, n0 = blockIdx.x * 128;
    const uint32_t sbase = s2u(smem);

    const __half* __restrict__ Ag = mode ? g_Actx : g_A;
    const __half* __restrict__ Bg = mode ? g_Bo   : g_Bqkv;

    const int lrow0 = tid >> 2;
    const int lseg  = (tid & 3) << 3;

    float acc[4][4][4];
#pragma unroll
    for (int i = 0; i < 4; i++)
#pragma unroll
        for (int j = 0; j < 4; j++)
#pragma unroll
            for (int q = 0; q < 4; q++) acc[i][j][q] = 0.f;

    {
        uint32_t dA = sbase, dB = sbase + TILEB;
#pragma unroll
        for (int u = 0; u < 2; u++) {
            int row = lrow0 + u * 64;
            CP_ASYNC16(dA + (row * LDS_ + lseg) * 2, Ag + (size_t)(m0 + row) * KTOT + lseg);
            CP_ASYNC16(dB + (row * LDS_ + lseg) * 2, Bg + (size_t)(n0 + row) * 1024 + lseg);
        }
        CP_COMMIT();
    }

    for (int c = 0; c < NCHUNK; c++) {
        CP_WAIT0();
        __syncthreads();

        if (c + 1 < NCHUNK) {
            uint32_t dA = sbase + ((c + 1) & 1) * 2 * TILEB;
            uint32_t dB = dA + TILEB;
            const int koff  = (c + 1) * 32 + lseg;
            const int koffB = koff & 1023;
#pragma unroll
            for (int u = 0; u < 2; u++) {
                int row = lrow0 + u * 64;
                CP_ASYNC16(dA + (row * LDS_ + lseg) * 2, Ag + (size_t)(m0 + row) * KTOT + koff);
                CP_ASYNC16(dB + (row * LDS_ + lseg) * 2, Bg + (size_t)(n0 + row) * 1024 + koffB);
            }
            CP_COMMIT();
        }

        const uint32_t bufA = sbase + (c & 1) * 2 * TILEB;
        const uint32_t bufB = bufA + TILEB;
        const int lr = lane & 15, lc = (lane >> 4) << 3;

#pragma unroll
        for (int ks = 0; ks < 2; ks++) {
            uint32_t a[4][4];
#pragma unroll
            for (int mi = 0; mi < 4; mi++) {
                uint32_t addr = bufA + ((wm * 64 + mi * 16 + lr) * LDS_ + ks * 16 + lc) * 2;
                LDMATX4(a[mi][0], a[mi][1], a[mi][2], a[mi][3], addr);
            }
            uint32_t b[4][2];
#pragma unroll
            for (int ni2 = 0; ni2 < 2; ni2++) {
                uint32_t r0, r1, r2, r3;
                uint32_t addr = bufB + ((wn * 32 + ni2 * 16 + lr) * LDS_ + ks * 16 + lc) * 2;
                LDMATX4(r0, r1, r2, r3, addr);
                b[2 * ni2][0] = r0;     b[2 * ni2][1] = r2;
                b[2 * ni2 + 1][0] = r1; b[2 * ni2 + 1][1] = r3;
            }
#pragma unroll
            for (int mi = 0; mi < 4; mi++)
#pragma unroll
                for (int ni = 0; ni < 4; ni++)
                    MMA16816H(acc[mi][ni], a[mi], b[ni]);
        }
        __syncthreads();
    }

    // -------- epilogue --------
    const int g  = lane >> 2;
    const int tc = (lane & 3) << 1;

    if (mode == 0) {
        const int proj = n0 >> 10;
        const float* bias = (proj == 0) ? b0p : (proj == 1) ? b1p : b2p;
#pragma unroll
        for (int mi = 0; mi < 4; mi++) {
            int m = m0 + wm * 64 + mi * 16 + g;
            int b_ = m >> 9, s_ = m & 511;
            int s2 = s_ + 8;
#pragma unroll
            for (int ni = 0; ni < 4; ni++) {
                int nl = (n0 & 1023) + wn * 32 + ni * 8 + tc;
                int hd = nl >> 6, d = nl & 63;
                int bh_ = b_ * HH + hd;
                float x0 = acc[mi][ni][0] + bias[nl];
                float x1 = acc[mi][ni][1] + bias[nl + 1];
                float x2 = acc[mi][ni][2] + bias[nl];
                float x3 = acc[mi][ni][3] + bias[nl + 1];
                __nv_bfloat16 hb0 = __float2bfloat16(x0), lb0 = __float2bfloat16(x0 - __bfloat162float(hb0));
                __nv_bfloat16 hb1 = __float2bfloat16(x1), lb1 = __float2bfloat16(x1 - __bfloat162float(hb1));
                __nv_bfloat16 hb2 = __float2bfloat16(x2), lb2 = __float2bfloat16(x2 - __bfloat162float(hb2));
                __nv_bfloat16 hb3 = __float2bfloat16(x3), lb3 = __float2bfloat16(x3 - __bfloat162float(hb3));
                if (proj < 2) {
                    __nv_bfloat16* ah = (proj == 0) ? qh : kh;
                    __nv_bfloat16* al = (proj == 0) ? ql : kl;
                    size_t o0 = ((size_t)bh_ * SS_ + s_) * DKV + d;
                    size_t o1 = o0 + 8 * DKV;
                    *(uint32_t*)(ah + o0) = pk2(hb0, hb1);
                    *(uint32_t*)(al + o0) = pk2(lb0, lb1);
                    *(uint32_t*)(ah + o1) = pk2(hb2, hb3);
                    *(uint32_t*)(al + o1) = pk2(lb2, lb3);
                } else {
                    size_t o = (size_t)bh_ * DKV * SS_ + (size_t)d * SS_;
                    vth[o + s_]       = hb0;  vtl[o + s_]       = lb0;
                    vth[o + SS_ + s_] = hb1;  vtl[o + SS_ + s_] = lb1;
                    vth[o + s2]       = hb2;  vtl[o + s2]       = lb2;
                    vth[o + SS_ + s2] = hb3;  vtl[o + SS_ + s2] = lb3;
                }
            }
        }
    } else {
#pragma unroll
        for (int mi = 0; mi < 4; mi++) {
            int m = m0 + wm * 64 + mi * 16 + g;
#pragma unroll
            for (int ni = 0; ni < 4; ni++) {
                int ncol = n0 + wn * 32 + ni * 8 + tc;
                float2 o0 = {acc[mi][ni][0] + b0p[ncol],
                             acc[mi][ni][1] + b0p[ncol + 1]};
                float2 o1 = {acc[mi][ni][2] + b0p[ncol],
                             acc[mi][ni][3] + b0p[ncol + 1]};
                *(float2*)(outp + (size_t)m * DM + ncol) = o0;
                *(float2*)(outp + (size_t)(m + 8) * DM + ncol) = o1;
            }
        }
    }
}

// ===========================================================================
// Scores GEMM (3-term bf16, 128x128 CTA, 6 chunks of 32, 2-stage) — R7 body
// mode 0 (content): grid(4 jt, 4 it, 128 bh): g_sc  = acc*SCALE + bias
// mode 1 (edge):    grid(4 jt, 512 i):        g_sc2 = acc*SCALE   (pure write)
// ===========================================================================
__global__ __launch_bounds__(256) void k_scores(const float* __restrict__ bias, int mode)
{
    __shared__ __align__(16) char smem[2 * 2 * TILEB];
    const int tid = threadIdx.x, wid = tid >> 5, lane = tid & 31;
    const int wm = wid >> 2, wn = wid & 3;
    const int j0 = blockIdx.x * 128;

    const __nv_bfloat16 *A0, *A1, *B0, *B1;
    size_t rsA;
    int i0 = 0, bh = 0, iE = 0;
    if (mode == 0) {
        i0 = blockIdx.y * 128; bh = blockIdx.z;
        A0 = qh + ((size_t)bh * SS_ + i0) * DKV;
        A1 = ql + ((size_t)bh * SS_ + i0) * DKV;
        B0 = kh + ((size_t)bh * SS_ + j0) * DKV;
        B1 = kl + ((size_t)bh * SS_ + j0) * DKV;
        rsA = DKV;
    } else {
        iE = blockIdx.y;
        A0 = qh + (size_t)iE * DKV;
        A1 = ql + (size_t)iE * DKV;
        B0 = ekh + ((size_t)iE * SS_ + j0) * DKV;
        B1 = ekl + ((size_t)iE * SS_ + j0) * DKV;
        rsA = (size_t)SS_ * DKV;
    }
    const __nv_bfloat16* At[3] = {A0, A0, A1};
    const __nv_bfloat16* Bt[3] = {B0, B1, B0};

    const uint32_t sbase = s2u(smem);
    const int lrow0 = tid >> 2, lseg = (tid & 3) << 3;

    float acc[4][4][4];
#pragma unroll
    for (int i = 0; i < 4; i++)
#pragma unroll
        for (int j = 0; j < 4; j++)
#pragma unroll
            for (int q = 0; q < 4; q++) acc[i][j][q] = 0.f;

    {
        uint32_t dA = sbase, dB = sbase + TILEB;
#pragma unroll
        for (int u = 0; u < 2; u++) {
            int row = lrow0 + u * 64;
            CP_ASYNC16(dA + (row * LDS_ + lseg) * 2, At[0] + (size_t)row * rsA + lseg);
            CP_ASYNC16(dB + (row * LDS_ + lseg) * 2, Bt[0] + (size_t)row * DKV + lseg);
        }
        CP_COMMIT();
    }

    for (int c = 0; c < 6; c++) {
        CP_WAIT0();
        __syncthreads();

        if (c + 1 < 6) {
            int t2 = (c + 1) >> 1, ko2 = ((c + 1) & 1) * 32;
            uint32_t dA = sbase + ((c + 1) & 1) * 2 * TILEB;
            uint32_t dB = dA + TILEB;
#pragma unroll
            for (int u = 0; u < 2; u++) {
                int row = lrow0 + u * 64;
                CP_ASYNC16(dA + (row * LDS_ + lseg) * 2, At[t2] + (size_t)row * rsA + ko2 + lseg);
                CP_ASYNC16(dB + (row * LDS_ + lseg) * 2, Bt[t2] + (size_t)row * DKV + ko2 + lseg);
            }
            CP_COMMIT();
        }

        const uint32_t bufA = sbase + (c & 1) * 2 * TILEB;
        const uint32_t bufB = bufA + TILEB;
        const int lr = lane & 15, lc = (lane >> 4) << 3;

#pragma unroll
        for (int ks = 0; ks < 2; ks++) {
            uint32_t a[4][4];
#pragma unroll
            for (int mi = 0; mi < 4; mi++) {
                uint32_t addr = bufA + ((wm * 64 + mi * 16 + lr) * LDS_ + ks * 16 + lc) * 2;
                LDMATX4(a[mi][0], a[mi][1], a[mi][2], a[mi][3], addr);
            }
            uint32_t b[4][2];
#pragma unroll
            for (int ni2 = 0; ni2 < 2; ni2++) {
                uint32_t r0, r1, r2, r3;
                uint32_t addr = bufB + ((wn * 32 + ni2 * 16 + lr) * LDS_ + ks * 16 + lc) * 2;
                LDMATX4(r0, r1, r2, r3, addr);
                b[2 * ni2][0] = r0;     b[2 * ni2][1] = r2;
                b[2 * ni2 + 1][0] = r1; b[2 * ni2 + 1][1] = r3;
            }
#pragma unroll
            for (int mi = 0; mi < 4; mi++)
#pragma unroll
                for (int ni = 0; ni < 4; ni++)
                    MMA16816(acc[mi][ni], a[mi], b[ni]);
        }
        __syncthreads();
    }

    const int g = lane >> 2, tc = (lane & 3) << 1;
#pragma unroll
    for (int mi = 0; mi < 4; mi++) {
        int m = wm * 64 + mi * 16 + g;
#pragma unroll
        for (int ni = 0; ni < 4; ni++) {
            int jc = j0 + wn * 32 + ni * 8 + tc;
            if (mode == 0) {
                size_t base0 = ((size_t)bh * SS_ + (i0 + m)) * SS_ + jc;
                size_t base1 = base0 + 8 * SS_;
                float2 o0 = {acc[mi][ni][0] * SCALE + bias[base0],
                             acc[mi][ni][1] * SCALE + bias[base0 + 1]};
                float2 o1 = {acc[mi][ni][2] * SCALE + bias[base1],
                             acc[mi][ni][3] * SCALE + bias[base1 + 1]};
                *(float2*)(g_sc + base0) = o0;
                *(float2*)(g_sc + base1) = o1;
            } else {
                size_t base0 = ((size_t)m * SS_ + iE) * SS_ + jc;
                size_t base1 = base0 + (size_t)8 * SS_ * SS_;
                float2 o0 = {acc[mi][ni][0] * SCALE, acc[mi][ni][1] * SCALE};
                float2 o1 = {acc[mi][ni][2] * SCALE, acc[mi][ni][3] * SCALE};
                *(float2*)(g_sc2 + base0) = o0;
                *(float2*)(g_sc2 + base1) = o1;
            }
        }
    }
}

// ===========================================================================
// Softmax + split: read g_sc + g_sc2, softmax, write wh/wl bf16
// ===========================================================================
__global__ __launch_bounds__(256) void k_softmax_split()
{
    const int warp = threadIdx.x >> 5, lane = threadIdx.x & 31;
    const size_t row = (size_t)blockIdx.x * 8 + warp;
    const float* p  = g_sc  + row * SS_;
    const float* p2 = g_sc2 + row * SS_;

    float4 v[4];
    float mx = -1e30f;
#pragma unroll
    for (int w = 0; w < 4; w++) {
        float4 a = *(const float4*)(p  + w * 128 + lane * 4);
        float4 b = *(const float4*)(p2 + w * 128 + lane * 4);
        v[w].x = a.x + b.x; v[w].y = a.y + b.y;
        v[w].z = a.z + b.z; v[w].w = a.w + b.w;
        mx = fmaxf(mx, fmaxf(fmaxf(v[w].x, v[w].y), fmaxf(v[w].z, v[w].w)));
    }
#pragma unroll
    for (int o = 16; o > 0; o >>= 1) mx = fmaxf(mx, __shfl_xor_sync(~0u, mx, o));

    float sum = 0.f;
#pragma unroll
    for (int w = 0; w < 4; w++) {
        v[w].x = __expf(v[w].x - mx); v[w].y = __expf(v[w].y - mx);
        v[w].z = __expf(v[w].z - mx); v[w].w = __expf(v[w].w - mx);
        sum += v[w].x + v[w].y + v[w].z + v[w].w;
    }
#pragma unroll
    for (int o = 16; o > 0; o >>= 1) sum += __shfl_xor_sync(~0u, sum, o);
    float r = 1.f / sum;
#pragma unroll
    for (int w = 0; w < 4; w++) {
        float f[4] = {v[w].x * r, v[w].y * r, v[w].z * r, v[w].w * r};
        uint32_t hu[2], lu[2];
#pragma unroll
        for (int pq = 0; pq < 2; pq++) {
            __nv_bfloat16 h0 = __float2bfloat16(f[2*pq]);
            __nv_bfloat16 h1 = __float2bfloat16(f[2*pq+1]);
            __nv_bfloat16 l0 = __float2bfloat16(f[2*pq]   - __bfloat162float(h0));
            __nv_bfloat16 l1 = __float2bfloat16(f[2*pq+1] - __bfloat162float(h1));
            hu[pq] = pk2(h0, h1); lu[pq] = pk2(l0, l1);
        }
        size_t off = row * SS_ + w * 128 + lane * 4;
        *(uint2*)(wh + off) = make_uint2(hu[0], hu[1]);
        *(uint2*)(wl + off) = make_uint2(lu[0], lu[1]);
    }
}

// ===========================================================================
// Context GEMM (3-term bf16, 128x64 CTA, 48 chunks of 32, 2-stage) — R7 body
// mode 0 (content): grid(4 it, 128 bh): g_ctx  = acc
// mode 1 (edge):    grid(512 i):        g_ctx2 = acc   (pure write)
// ===========================================================================
#define CT_A_TILEB (128 * LDS_ * 2)
#define CT_B_TILEB (64 * LDS_ * 2)
#define CT_STAGE   (CT_A_TILEB + CT_B_TILEB)

__global__ __launch_bounds__(256) void k_ctx(int mode)
{
    __shared__ __align__(16) char smem[2 * CT_STAGE];
    const int tid = threadIdx.x, wid = tid >> 5, lane = tid & 31;
    const int wm = wid >> 1, wn = wid & 1;

    const __nv_bfloat16 *A0, *A1, *B0, *B1;
    size_t rsA;
    int i0 = 0, bh = 0, iE = 0;
    if (mode == 0) {
        bh = blockIdx.y; i0 = blockIdx.x * 128;
        A0 = wh + (size_t)bh * SS_ * SS_ + (size_t)i0 * SS_;
        A1 = wl + (size_t)bh * SS_ * SS_ + (size_t)i0 * SS_;
        B0 = vth + (size_t)bh * DKV * SS_;
        B1 = vtl + (size_t)bh * DKV * SS_;
        rsA = SS_;
    } else {
        iE = blockIdx.x;
        A0 = wh + (size_t)iE * SS_;
        A1 = wl + (size_t)iE * SS_;
        B0 = evth + (size_t)iE * DKV * SS_;
        B1 = evtl + (size_t)iE * DKV * SS_;
        rsA = (size_t)SS_ * SS_;
    }
    const __nv_bfloat16* At[3] = {A0, A0, A1};
    const __nv_bfloat16* Bt[3] = {B0, B1, B0};

    const uint32_t sbase = s2u(smem);
    const int arow = tid >> 1, aseg = (tid & 1) << 4;
    const int brow = tid >> 2, bseg = (tid & 3) << 3;

    float acc[2][4][4];
#pragma unroll
    for (int i = 0; i < 2; i++)
#pragma unroll
        for (int j = 0; j < 4; j++)
#pragma unroll
            for (int q = 0; q < 4; q++) acc[i][j][q] = 0.f;

    {
        uint32_t dA = sbase, dB = sbase + CT_A_TILEB;
        CP_ASYNC16(dA + (arow * LDS_ + aseg) * 2,     At[0] + (size_t)arow * rsA + aseg);
        CP_ASYNC16(dA + (arow * LDS_ + aseg + 8) * 2, At[0] + (size_t)arow * rsA + aseg + 8);
        CP_ASYNC16(dB + (brow * LDS_ + bseg) * 2,     Bt[0] + (size_t)brow * SS_ + bseg);
        CP_COMMIT();
    }

    for (int c = 0; c < 48; c++) {
        CP_WAIT0();
        __syncthreads();

        if (c + 1 < 48) {
            int t2 = (c + 1) >> 4, ko2 = ((c + 1) & 15) * 32;
            uint32_t dA = sbase + ((c + 1) & 1) * CT_STAGE;
            uint32_t dB = dA + CT_A_TILEB;
            CP_ASYNC16(dA + (arow * LDS_ + aseg) * 2,     At[t2] + (size_t)arow * rsA + ko2 + aseg);
            CP_ASYNC16(dA + (arow * LDS_ + aseg + 8) * 2, At[t2] + (size_t)arow * rsA + ko2 + aseg + 8);
            CP_ASYNC16(dB + (brow * LDS_ + bseg) * 2,     Bt[t2] + (size_t)brow * SS_ + ko2 + bseg);
            CP_COMMIT();
        }

        const uint32_t bufA = sbase + (c & 1) * CT_STAGE;
        const uint32_t bufB = bufA + CT_A_TILEB;
        const int lr = lane & 15, lc = (lane >> 4) << 3;

#pragma unroll
        for (int ks = 0; ks < 2; ks++) {
            uint32_t a[2][4];
#pragma unroll
            for (int mi = 0; mi < 2; mi++) {
                uint32_t addr = bufA + ((wm * 32 + mi * 16 + lr) * LDS_ + ks * 16 + lc) * 2;
                LDMATX4(a[mi][0], a[mi][1], a[mi][2], a[mi][3], addr);
            }
            uint32_t b[4][2];
#pragma unroll
            for (int ni2 = 0; ni2 < 2; ni2++) {
                uint32_t r0, r1, r2, r3;
                uint32_t addr = bufB + ((wn * 32 + ni2 * 16 + lr) * LDS_ + ks * 16 + lc) * 2;
                LDMATX4(r0, r1, r2, r3, addr);
                b[2 * ni2][0] = r0;     b[2 * ni2][1] = r2;
                b[2 * ni2 + 1][0] = r1; b[2 * ni2 + 1][1] = r3;
            }
#pragma unroll
            for (int mi = 0; mi < 2; mi++)
#pragma unroll
                for (int ni = 0; ni < 4; ni++)
                    MMA16816(acc[mi][ni], a[mi], b[ni]);
        }
        __syncthreads();
    }

    const int g = lane >> 2, tc = (lane & 3) << 1;
#pragma unroll
    for (int mi = 0; mi < 2; mi++) {
        int m = wm * 32 + mi * 16 + g;
#pragma unroll
        for (int ni = 0; ni < 4; ni++) {
            int ncol = wn * 32 + ni * 8 + tc;
            if (mode == 0) {
                int i = i0 + m;
                size_t a0 = ((size_t)(bh >> 4) * SS_ + i) * DM + (bh & 15) * DKV + ncol;
                size_t a1 = a0 + (size_t)8 * DM;
                *(float2*)(g_ctx + a0) = make_float2(acc[mi][ni][0], acc[mi][ni][1]);
                *(float2*)(g_ctx + a1) = make_float2(acc[mi][ni][2], acc[mi][ni][3]);
            } else {
                int bh0 = m, bh1 = m + 8;
                size_t a0 = ((size_t)(bh0 >> 4) * SS_ + iE) * DM + (bh0 & 15) * DKV + ncol;
                size_t a1 = ((size_t)(bh1 >> 4) * SS_ + iE) * DM + (bh1 & 15) * DKV + ncol;
                *(float2*)(g_ctx2 + a0) = make_float2(acc[mi][ni][0], acc[mi][ni][1]);
                *(float2*)(g_ctx2 + a1) = make_float2(acc[mi][ni][2], acc[mi][ni][3]);
            }
        }
    }
}

// ===========================================================================
// Launcher — R7 topology (best measured): edge splits ∥ projections;
// content ∥ edge score/context pairs on separate buffers.
// ===========================================================================
extern "C" void kernel_launch(void* const* d_in, const int* in_sizes, int n_in,
                              void* d_out, int out_size)
{
    const float* queries     = (const float*)d_in[0];
    const float* edges_key   = (const float*)d_in[1];
    const float* edges_value = (const float*)d_in[2];
    const float* attn_bias   = (const float*)d_in[3];
    const float* Wq = (const float*)d_in[4];
    const float* bq = (const float*)d_in[5];
    const float* Wk = (const float*)d_in[6];
    const float* bk = (const float*)d_in[7];
    const float* Wv = (const float*)d_in[8];
    const float* bv = (const float*)d_in[9];
    const float* Wo = (const float*)d_in[10];
    const float* bo = (const float*)d_in[11];
    float* out = (float*)d_out;

    static cudaStream_t s2 = nullptr, s3 = nullptr;
    static cudaEvent_t evFork = nullptr, evEdgeSplit = nullptr, evQKV = nullptr,
                       evEdgeSc = nullptr, evSM = nullptr, evCtx1 = nullptr;
    if (!s2) {
        cudaStreamCreateWithFlags(&s2, cudaStreamNonBlocking);
        cudaStreamCreateWithFlags(&s3, cudaStreamNonBlocking);
        cudaEventCreateWithFlags(&evFork,      cudaEventDisableTiming);
        cudaEventCreateWithFlags(&evEdgeSplit, cudaEventDisableTiming);
        cudaEventCreateWithFlags(&evQKV,       cudaEventDisableTiming);
        cudaEventCreateWithFlags(&evEdgeSc,    cudaEventDisableTiming);
        cudaEventCreateWithFlags(&evSM,        cudaEventDisableTiming);
        cudaEventCreateWithFlags(&evCtx1,      cudaEventDisableTiming);
    }

    cudaStream_t st = 0;
    cudaStreamCaptureStatus cs = cudaStreamCaptureStatusNone;
    if (cudaStreamIsCapturing(cudaStreamPerThread, &cs) == cudaSuccess &&
        cs == cudaStreamCaptureStatusActive)
        st = cudaStreamPerThread;

    // fork: edge-tensor splits overlap the projection path
    cudaEventRecord(evFork, st);
    cudaStreamWaitEvent(s2, evFork, 0);
    k_split_ek <<<8192, 256, 0, s2>>>(edges_key);
    k_split_evt<<<dim3(16, 2, 512), 256, 0, s2>>>(edges_value);
    cudaEventRecord(evEdgeSplit, s2);

    // projection path (main stream) — fp16 2-term
    k_split <<<2048, 256, 0, st>>>(queries, 0);
    k_wsplit<<<dim3(4, 128, 4), 256, 0, st>>>(Wq, Wk, Wv, Wo);
    k_gemm_f16<<<dim3(24, 32), 256, 0, st>>>(bq, bk, bv, nullptr, 0);
    cudaEventRecord(evQKV, st);

    // content scores (st) ∥ edge scores (s3, independent buffer g_sc2)
    cudaStreamWaitEvent(s3, evQKV, 0);
    cudaStreamWaitEvent(s3, evEdgeSplit, 0);
    k_scores<<<dim3(4, 512), 256, 0, s3>>>(nullptr, 1);
    cudaEventRecord(evEdgeSc, s3);

    k_scores<<<dim3(4, 4, 128), 256, 0, st>>>(attn_bias, 0);

    // softmax needs both score buffers
    cudaStreamWaitEvent(st, evEdgeSc, 0);
    k_softmax_split<<<8192, 256, 0, st>>>();
    cudaEventRecord(evSM, st);

    // content context (st) ∥ edge context (s3, independent buffer g_ctx2)
    cudaStreamWaitEvent(s3, evSM, 0);
    k_ctx<<<dim3(512), 256, 0, s3>>>(1);
    cudaEventRecord(evCtx1, s3);

    k_ctx<<<dim3(4, 128), 256, 0, st>>>(0);

    // output projection (needs both context buffers) — fp16 2-term
    cudaStreamWaitEvent(st, evCtx1, 0);
    k_split<<<2048, 256, 0, st>>>(nullptr, 1);
    k_gemm_f16<<<dim3(8, 32), 256, 0, st>>>(bo, nullptr, nullptr, out, 1);
}

// round 11
// speedup vs baseline: 1.2787x; 1.0748x over previous
#include <cuda_runtime.h>
#include <cuda_bf16.h>
#include <cuda_fp16.h>
#include <cstdint>

// ---------------------------------------------------------------------------
// Problem constants: B=8, S=512, D_MODEL=1024, H=16, DK=DV=64, BH=128
// ---------------------------------------------------------------------------
#define BB   8
#define SS_  512
#define DM   1024
#define HH   16
#define DKV  64
#define BH   128
#define SCALE 0.125f

// ---------------------------------------------------------------------------
// Scratch (device globals)
// ---------------------------------------------------------------------------
__device__ float g_sc  [(size_t)BH * SS_ * SS_];   // content scores + bias
__device__ float g_sc2 [(size_t)BH * SS_ * SS_];   // edge scores
__device__ float g_ctx [(size_t)BB * SS_ * DM];    // content context
__device__ float g_ctx2[(size_t)BB * SS_ * DM];    // edge context

// projection staging: A = [Xfh | Xfl] fp16, B = Wf fp16
__device__ __align__(16) __half g_A   [(size_t)4096 * 2048];
__device__ __align__(16) __half g_Actx[(size_t)4096 * 2048];
__device__ __align__(16) __half g_Bqkv[(size_t)3072 * 1024];
__device__ __align__(16) __half g_Bo  [(size_t)1024 * 1024];

// attention operands, fp16: q/w split hi/lo (A-side, exact), k/v/ek/ev single
__device__ __align__(16) __half qh [(size_t)BH * SS_ * DKV];
__device__ __align__(16) __half ql [(size_t)BH * SS_ * DKV];
__device__ __align__(16) __half kh [(size_t)BH * SS_ * DKV];
__device__ __align__(16) __half vth[(size_t)BH * DKV * SS_];   // [bh,d,s]
__device__ __align__(16) __half ekh [(size_t)SS_ * SS_ * DKV]; // [i,j,d]
__device__ __align__(16) __half evth[(size_t)SS_ * DKV * SS_]; // [i,d,j]
__device__ __align__(16) __half wh [(size_t)BH * SS_ * SS_];   // [bh,i,j]
__device__ __align__(16) __half wl [(size_t)BH * SS_ * SS_];

__device__ __forceinline__ uint32_t s2u(const void* p) {
    uint32_t a;
    asm("{ .reg .u64 t; cvta.to.shared.u64 t, %1; cvt.u32.u64 %0, t; }"
        : "=r"(a) : "l"(p));
    return a;
}
__device__ __forceinline__ uint32_t pk2h(__half a, __half b) {
    return (uint32_t)__half_as_ushort(a) | ((uint32_t)__half_as_ushort(b) << 16);
}

#define CP_ASYNC16(dst, src) \
    asm volatile("cp.async.cg.shared.global [%0], [%1], 16;" :: "r"(dst), "l"(src) : "memory")
#define CP_COMMIT() asm volatile("cp.async.commit_group;" ::: "memory")
#define CP_WAIT0()  asm volatile("cp.async.wait_group 0;" ::: "memory")

#define LDMATX4(r0, r1, r2, r3, addr) \
    asm volatile("ldmatrix.sync.aligned.m8n8.x4.shared.b16 {%0,%1,%2,%3}, [%4];" \
        : "=r"(r0), "=r"(r1), "=r"(r2), "=r"(r3) : "r"(addr))

#define MMA16816H(c, a, b) \
    asm volatile("mma.sync.aligned.m16n8k16.row.col.f32.f16.f16.f32 " \
        "{%0,%1,%2,%3}, {%4,%5,%6,%7}, {%8,%9}, {%0,%1,%2,%3};" \
        : "+f"((c)[0]), "+f"((c)[1]), "+f"((c)[2]), "+f"((c)[3]) \
        : "r"((a)[0]), "r"((a)[1]), "r"((a)[2]), "r"((a)[3]), \
          "r"((b)[0]), "r"((b)[1]))

#define LDS_   40                 // padded row stride in 16-bit elems (80 bytes)
#define TILEB  (128 * LDS_ * 2)   // 10240 bytes

// ===========================================================================
// fp16 hi/lo split: fp32 [4096,1024] -> [4096][Xfh(1024)|Xfl(1024)]
// which=0: queries -> g_A ; which=1: g_ctx+g_ctx2 -> g_Actx
// ===========================================================================
__global__ __launch_bounds__(256) void k_split(const float* __restrict__ src_in, int which)
{
    int idx = blockIdx.x * 256 + threadIdx.x;
    int r = idx >> 7;
    int c0 = (idx & 127) << 3;
    float f[8];
    if (which == 0) {
        const float* s = src_in + (size_t)r * 1024 + c0;
        float4 v0 = *(const float4*)(s);
        float4 v1 = *(const float4*)(s + 4);
        f[0]=v0.x; f[1]=v0.y; f[2]=v0.z; f[3]=v0.w;
        f[4]=v1.x; f[5]=v1.y; f[6]=v1.z; f[7]=v1.w;
    } else {
        const float* s0 = (const float*)g_ctx  + (size_t)r * 1024 + c0;
        const float* s1 = (const float*)g_ctx2 + (size_t)r * 1024 + c0;
        float4 a0 = *(const float4*)(s0), a1 = *(const float4*)(s0 + 4);
        float4 b0 = *(const float4*)(s1), b1 = *(const float4*)(s1 + 4);
        f[0]=a0.x+b0.x; f[1]=a0.y+b0.y; f[2]=a0.z+b0.z; f[3]=a0.w+b0.w;
        f[4]=a1.x+b1.x; f[5]=a1.y+b1.y; f[6]=a1.z+b1.z; f[7]=a1.w+b1.w;
    }
    __half* dst = which ? g_Actx : g_A;
    uint4 H, L;
    uint32_t hu[4], lu[4];
#pragma unroll
    for (int i = 0; i < 4; i++) {
        __half h0 = __float2half_rn(f[2*i]);
        __half h1 = __float2half_rn(f[2*i+1]);
        __half l0 = __float2half_rn(f[2*i]   - __half2float(h0));
        __half l1 = __float2half_rn(f[2*i+1] - __half2float(h1));
        hu[i] = pk2h(h0, h1); lu[i] = pk2h(l0, l1);
    }
    H.x = hu[0]; H.y = hu[1]; H.z = hu[2]; H.w = hu[3];
    L.x = lu[0]; L.y = lu[1]; L.z = lu[2]; L.w = lu[3];
    __half* row = dst + (size_t)r * 2048;
    *(uint4*)(row + c0)        = H;
    *(uint4*)(row + 1024 + c0) = L;
}

// ===========================================================================
// Weight fp16 transpose (4 weights): W[1024k,1024n] -> Bf[n][1024] fp16
// ===========================================================================
__global__ __launch_bounds__(256) void k_wsplit(
    const float* __restrict__ W0, const float* __restrict__ W1,
    const float* __restrict__ W2, const float* __restrict__ W3)
{
    const int slot = blockIdx.z;
    const float* W = (slot == 0) ? W0 : (slot == 1) ? W1 : (slot == 2) ? W2 : W3;
    __half* dst = (slot < 3) ? (g_Bqkv + (size_t)slot * 1024 * 1024) : g_Bo;
    int nl = blockIdx.x * 256 + threadIdx.x;
    int k0 = blockIdx.y << 3;
    uint32_t hu[4];
#pragma unroll
    for (int i = 0; i < 4; i++) {
        __half h0 = __float2half_rn(W[(size_t)(k0 + 2*i)     * 1024 + nl]);
        __half h1 = __float2half_rn(W[(size_t)(k0 + 2*i + 1) * 1024 + nl]);
        hu[i] = pk2h(h0, h1);
    }
    uint4 H; H.x = hu[0]; H.y = hu[1]; H.z = hu[2]; H.w = hu[3];
    *(uint4*)(dst + (size_t)nl * 1024 + k0) = H;
}

// ===========================================================================
// EK convert: fp32 [i,j,64] -> ekh fp16 (single, elementwise)
// ===========================================================================
__global__ __launch_bounds__(256) void k_split_ek(const float* __restrict__ EK)
{
    size_t base = ((size_t)blockIdx.x * 256 + threadIdx.x) * 8;
    float4 v0 = *(const float4*)(EK + base);
    float4 v1 = *(const float4*)(EK + base + 4);
    float f[8] = {v0.x, v0.y, v0.z, v0.w, v1.x, v1.y, v1.z, v1.w};
    uint32_t hu[4];
#pragma unroll
    for (int i = 0; i < 4; i++)
        hu[i] = pk2h(__float2half_rn(f[2*i]), __float2half_rn(f[2*i+1]));
    uint4 H; H.x = hu[0]; H.y = hu[1]; H.z = hu[2]; H.w = hu[3];
    *(uint4*)(ekh + base) = H;
}

// ===========================================================================
// EV transpose-convert: fp32 [i,j,64] -> evth fp16 [i,64,512] (single)
// ===========================================================================
__global__ __launch_bounds__(256) void k_split_evt(const float* __restrict__ EV)
{
    __shared__ float ts[32][33];
    const int jt = blockIdx.x, dt = blockIdx.y, i = blockIdx.z;
    const int t = threadIdx.x;
    const int r = t >> 3, c0 = (t & 7) << 2;

    float4 v = *(const float4*)(EV + ((size_t)(i * SS_ + jt * 32 + r)) * DKV + dt * 32 + c0);
    ts[r][c0 + 0] = v.x; ts[r][c0 + 1] = v.y;
    ts[r][c0 + 2] = v.z; ts[r][c0 + 3] = v.w;
    __syncthreads();

    uint32_t hu[2];
#pragma unroll
    for (int p = 0; p < 2; p++)
        hu[p] = pk2h(__float2half_rn(ts[c0 + 2*p][r]), __float2half_rn(ts[c0 + 2*p + 1][r]));
    size_t off = ((size_t)i * DKV + dt * 32 + r) * SS_ + jt * 32 + c0;
    *(uint2*)(evth + off) = make_uint2(hu[0], hu[1]);
}

// ===========================================================================
// fp16 mma.sync GEMM (projections): C[4096,N] = [Xfh|Xfl] @ [Wf;Wf]^T
// K=2048 on A side; B K-index masked (&1023). 2-stage cp.async, 128x128 CTA.
// mode 0: QKV -> q hi/lo, k single, v^T single; mode 1: OUT -> outp
// ===========================================================================
#define KTOT   2048
#define NCHUNK 64

__global__ __launch_bounds__(256) void k_gemm_f16(
    const float* __restrict__ b0p, const float* __restrict__ b1p,
    const float* __restrict__ b2p, float* __restrict__ outp, int mode)
{
    __shared__ __align__(16) char smem[2 * 2 * TILEB];

    const int tid  = threadIdx.x;
    const int wid  = tid >> 5, lane = tid & 31;
    const int wm   = wid >> 2, wn = wid & 3;
    const int m0   = blockIdx.y * 128, n0 = blockIdx.x * 128;
    const uint32_t sbase = s2u(smem);

    const __half* __restrict__ Ag = mode ? g_Actx : g_A;
    const __half* __restrict__ Bg = mode ? g_Bo   : g_Bqkv;

    const int lrow0 = tid >> 2;
    const int lseg  = (tid & 3) << 3;

    float acc[4][4][4];
#pragma unroll
    for (int i = 0; i < 4; i++)
#pragma unroll
        for (int j = 0; j < 4; j++)
#pragma unroll
            for (int q = 0; q < 4; q++) acc[i][j][q] = 0.f;

    {
        uint32_t dA = sbase, dB = sbase + TILEB;
#pragma unroll
        for (int u = 0; u < 2; u++) {
            int row = lrow0 + u * 64;
            CP_ASYNC16(dA + (row * LDS_ + lseg) * 2, Ag + (size_t)(m0 + row) * KTOT + lseg);
            CP_ASYNC16(dB + (row * LDS_ + lseg) * 2, Bg + (size_t)(n0 + row) * 1024 + lseg);
        }
        CP_COMMIT();
    }

    for (int c = 0; c < NCHUNK; c++) {
        CP_WAIT0();
        __syncthreads();

        if (c + 1 < NCHUNK) {
            uint32_t dA = sbase + ((c + 1) & 1) * 2 * TILEB;
            uint32_t dB = dA + TILEB;
            const int koff  = (c + 1) * 32 + lseg;
            const int koffB = koff & 1023;
#pragma unroll
            for (int u = 0; u < 2; u++) {
                int row = lrow0 + u * 64;
                CP_ASYNC16(dA + (row * LDS_ + lseg) * 2, Ag + (size_t)(m0 + row) * KTOT + koff);
                CP_ASYNC16(dB + (row * LDS_ + lseg) * 2, Bg + (size_t)(n0 + row) * 1024 + koffB);
            }
            CP_COMMIT();
        }

        const uint32_t bufA = sbase + (c & 1) * 2 * TILEB;
        const uint32_t bufB = bufA + TILEB;
        const int lr = lane & 15, lc = (lane >> 4) << 3;

#pragma unroll
        for (int ks = 0; ks < 2; ks++) {
            uint32_t a[4][4];
#pragma unroll
            for (int mi = 0; mi < 4; mi++) {
                uint32_t addr = bufA + ((wm * 64 + mi * 16 + lr) * LDS_ + ks * 16 + lc) * 2;
                LDMATX4(a[mi][0], a[mi][1], a[mi][2], a[mi][3], addr);
            }
            uint32_t b[4][2];
#pragma unroll
            for (int ni2 = 0; ni2 < 2; ni2++) {
                uint32_t r0, r1, r2, r3;
                uint32_t addr = bufB + ((wn * 32 + ni2 * 16 + lr) * LDS_ + ks * 16 + lc) * 2;
                LDMATX4(r0, r1, r2, r3, addr);
                b[2 * ni2][0] = r0;     b[2 * ni2][1] = r2;
                b[2 * ni2 + 1][0] = r1; b[2 * ni2 + 1][1] = r3;
            }
#pragma unroll
            for (int mi = 0; mi < 4; mi++)
#pragma unroll
                for (int ni = 0; ni < 4; ni++)
                    MMA16816H(acc[mi][ni], a[mi], b[ni]);
        }
        __syncthreads();
    }

    // -------- epilogue --------
    const int g  = lane >> 2;
    const int tc = (lane & 3) << 1;

    if (mode == 0) {
        const int proj = n0 >> 10;
        const float* bias = (proj == 0) ? b0p : (proj == 1) ? b1p : b2p;
#pragma unroll
        for (int mi = 0; mi < 4; mi++) {
            int m = m0 + wm * 64 + mi * 16 + g;
            int b_ = m >> 9, s_ = m & 511;
            int s2 = s_ + 8;
#pragma unroll
            for (int ni = 0; ni < 4; ni++) {
                int nl = (n0 & 1023) + wn * 32 + ni * 8 + tc;
                int hd = nl >> 6, d = nl & 63;
                int bh_ = b_ * HH + hd;
                float x0 = acc[mi][ni][0] + bias[nl];
                float x1 = acc[mi][ni][1] + bias[nl + 1];
                float x2 = acc[mi][ni][2] + bias[nl];
                float x3 = acc[mi][ni][3] + bias[nl + 1];
                __half h0 = __float2half_rn(x0);
                __half h1 = __float2half_rn(x1);
                __half h2 = __float2half_rn(x2);
                __half h3 = __float2half_rn(x3);
                if (proj == 0) {
                    __half l0 = __float2half_rn(x0 - __half2float(h0));
                    __half l1 = __float2half_rn(x1 - __half2float(h1));
                    __half l2 = __float2half_rn(x2 - __half2float(h2));
                    __half l3 = __float2half_rn(x3 - __half2float(h3));
                    size_t o0 = ((size_t)bh_ * SS_ + s_) * DKV + d;
                    size_t o1 = o0 + 8 * DKV;
                    *(uint32_t*)(qh + o0) = pk2h(h0, h1);
                    *(uint32_t*)(ql + o0) = pk2h(l0, l1);
                    *(uint32_t*)(qh + o1) = pk2h(h2, h3);
                    *(uint32_t*)(ql + o1) = pk2h(l2, l3);
                } else if (proj == 1) {
                    size_t o0 = ((size_t)bh_ * SS_ + s_) * DKV + d;
                    size_t o1 = o0 + 8 * DKV;
                    *(uint32_t*)(kh + o0) = pk2h(h0, h1);
                    *(uint32_t*)(kh + o1) = pk2h(h2, h3);
                } else {
                    size_t o = (size_t)bh_ * DKV * SS_ + (size_t)d * SS_;
                    vth[o + s_]       = h0;
                    vth[o + SS_ + s_] = h1;
                    vth[o + s2]       = h2;
                    vth[o + SS_ + s2] = h3;
                }
            }
        }
    } else {
#pragma unroll
        for (int mi = 0; mi < 4; mi++) {
            int m = m0 + wm * 64 + mi * 16 + g;
#pragma unroll
            for (int ni = 0; ni < 4; ni++) {
                int ncol = n0 + wn * 32 + ni * 8 + tc;
                float2 o0 = {acc[mi][ni][0] + b0p[ncol],
                             acc[mi][ni][1] + b0p[ncol + 1]};
                float2 o1 = {acc[mi][ni][2] + b0p[ncol],
                             acc[mi][ni][3] + b0p[ncol + 1]};
                *(float2*)(outp + (size_t)m * DM + ncol) = o0;
                *(float2*)(outp + (size_t)(m + 8) * DM + ncol) = o1;
            }
        }
    }
}

// ===========================================================================
// Scores GEMM (fp16 2-term: [q_fh|q_fl] @ B_f, K=128, 4 chunks of 32)
// mode 0 (content): grid(4 jt, 4 it, 128 bh): g_sc  = acc*SCALE + bias
// mode 1 (edge):    grid(4 jt, 512 i):        g_sc2 = acc*SCALE (pure write)
// ===========================================================================
__global__ __launch_bounds__(256) void k_scores(const float* __restrict__ bias, int mode)
{
    __shared__ __align__(16) char smem[2 * 2 * TILEB];
    const int tid = threadIdx.x, wid = tid >> 5, lane = tid & 31;
    const int wm = wid >> 2, wn = wid & 3;
    const int j0 = blockIdx.x * 128;

    const __half *A0, *A1, *B0;
    size_t rsA;
    int i0 = 0, bh = 0, iE = 0;
    if (mode == 0) {
        i0 = blockIdx.y * 128; bh = blockIdx.z;
        A0 = qh + ((size_t)bh * SS_ + i0) * DKV;
        A1 = ql + ((size_t)bh * SS_ + i0) * DKV;
        B0 = kh + ((size_t)bh * SS_ + j0) * DKV;
        rsA = DKV;
    } else {
        iE = blockIdx.y;
        A0 = qh + (size_t)iE * DKV;
        A1 = ql + (size_t)iE * DKV;
        B0 = ekh + ((size_t)iE * SS_ + j0) * DKV;
        rsA = (size_t)SS_ * DKV;
    }
    const __half* At[2] = {A0, A1};

    const uint32_t sbase = s2u(smem);
    const int lrow0 = tid >> 2, lseg = (tid & 3) << 3;

    float acc[4][4][4];
#pragma unroll
    for (int i = 0; i < 4; i++)
#pragma unroll
        for (int j = 0; j < 4; j++)
#pragma unroll
            for (int q = 0; q < 4; q++) acc[i][j][q] = 0.f;

    {
        uint32_t dA = sbase, dB = sbase + TILEB;
#pragma unroll
        for (int u = 0; u < 2; u++) {
            int row = lrow0 + u * 64;
            CP_ASYNC16(dA + (row * LDS_ + lseg) * 2, At[0] + (size_t)row * rsA + lseg);
            CP_ASYNC16(dB + (row * LDS_ + lseg) * 2, B0 + (size_t)row * DKV + lseg);
        }
        CP_COMMIT();
    }

    for (int c = 0; c < 4; c++) {
        CP_WAIT0();
        __syncthreads();

        if (c + 1 < 4) {
            int t2 = (c + 1) >> 1, ko2 = ((c + 1) & 1) * 32;
            uint32_t dA = sbase + ((c + 1) & 1) * 2 * TILEB;
            uint32_t dB = dA + TILEB;
#pragma unroll
            for (int u = 0; u < 2; u++) {
                int row = lrow0 + u * 64;
                CP_ASYNC16(dA + (row * LDS_ + lseg) * 2, At[t2] + (size_t)row * rsA + ko2 + lseg);
                CP_ASYNC16(dB + (row * LDS_ + lseg) * 2, B0 + (size_t)row * DKV + ko2 + lseg);
            }
            CP_COMMIT();
        }

        const uint32_t bufA = sbase + (c & 1) * 2 * TILEB;
        const uint32_t bufB = bufA + TILEB;
        const int lr = lane & 15, lc = (lane >> 4) << 3;

#pragma unroll
        for (int ks = 0; ks < 2; ks++) {
            uint32_t a[4][4];
#pragma unroll
            for (int mi = 0; mi < 4; mi++) {
                uint32_t addr = bufA + ((wm * 64 + mi * 16 + lr) * LDS_ + ks * 16 + lc) * 2;
                LDMATX4(a[mi][0], a[mi][1], a[mi][2], a[mi][3], addr);
            }
            uint32_t b[4][2];
#pragma unroll
            for (int ni2 = 0; ni2 < 2; ni2++) {
                uint32_t r0, r1, r2, r3;
                uint32_t addr = bufB + ((wn * 32 + ni2 * 16 + lr) * LDS_ + ks * 16 + lc) * 2;
                LDMATX4(r0, r1, r2, r3, addr);
                b[2 * ni2][0] = r0;     b[2 * ni2][1] = r2;
                b[2 * ni2 + 1][0] = r1; b[2 * ni2 + 1][1] = r3;
            }
#pragma unroll
            for (int mi = 0; mi < 4; mi++)
#pragma unroll
                for (int ni = 0; ni < 4; ni++)
                    MMA16816H(acc[mi][ni], a[mi], b[ni]);
        }
        __syncthreads();
    }

    const int g = lane >> 2, tc = (lane & 3) << 1;
#pragma unroll
    for (int mi = 0; mi < 4; mi++) {
        int m = wm * 64 + mi * 16 + g;
#pragma unroll
        for (int ni = 0; ni < 4; ni++) {
            int jc = j0 + wn * 32 + ni * 8 + tc;
            if (mode == 0) {
                size_t base0 = ((size_t)bh * SS_ + (i0 + m)) * SS_ + jc;
                size_t base1 = base0 + 8 * SS_;
                float2 o0 = {acc[mi][ni][0] * SCALE + bias[base0],
                             acc[mi][ni][1] * SCALE + bias[base0 + 1]};
                float2 o1 = {acc[mi][ni][2] * SCALE + bias[base1],
                             acc[mi][ni][3] * SCALE + bias[base1 + 1]};
                *(float2*)(g_sc + base0) = o0;
                *(float2*)(g_sc + base1) = o1;
            } else {
                size_t base0 = ((size_t)m * SS_ + iE) * SS_ + jc;
                size_t base1 = base0 + (size_t)8 * SS_ * SS_;
                float2 o0 = {acc[mi][ni][0] * SCALE, acc[mi][ni][1] * SCALE};
                float2 o1 = {acc[mi][ni][2] * SCALE, acc[mi][ni][3] * SCALE};
                *(float2*)(g_sc2 + base0) = o0;
                *(float2*)(g_sc2 + base1) = o1;
            }
        }
    }
}

// ===========================================================================
// Softmax + split: read g_sc + g_sc2, softmax, write wh/wl fp16
// ===========================================================================
__global__ __launch_bounds__(256) void k_softmax_split()
{
    const int warp = threadIdx.x >> 5, lane = threadIdx.x & 31;
    const size_t row = (size_t)blockIdx.x * 8 + warp;
    const float* p  = g_sc  + row * SS_;
    const float* p2 = g_sc2 + row * SS_;

    float4 v[4];
    float mx = -1e30f;
#pragma unroll
    for (int w = 0; w < 4; w++) {
        float4 a = *(const float4*)(p  + w * 128 + lane * 4);
        float4 b = *(const float4*)(p2 + w * 128 + lane * 4);
        v[w].x = a.x + b.x; v[w].y = a.y + b.y;
        v[w].z = a.z + b.z; v[w].w = a.w + b.w;
        mx = fmaxf(mx, fmaxf(fmaxf(v[w].x, v[w].y), fmaxf(v[w].z, v[w].w)));
    }
#pragma unroll
    for (int o = 16; o > 0; o >>= 1) mx = fmaxf(mx, __shfl_xor_sync(~0u, mx, o));

    float sum = 0.f;
#pragma unroll
    for (int w = 0; w < 4; w++) {
        v[w].x = __expf(v[w].x - mx); v[w].y = __expf(v[w].y - mx);
        v[w].z = __expf(v[w].z - mx); v[w].w = __expf(v[w].w - mx);
        sum += v[w].x + v[w].y + v[w].z + v[w].w;
    }
#pragma unroll
    for (int o = 16; o > 0; o >>= 1) sum += __shfl_xor_sync(~0u, sum, o);
    float r = 1.f / sum;
#pragma unroll
    for (int w = 0; w < 4; w++) {
        float f[4] = {v[w].x * r, v[w].y * r, v[w].z * r, v[w].w * r};
        uint32_t hu[2], lu[2];
#pragma unroll
        for (int pq = 0; pq < 2; pq++) {
            __half h0 = __float2half_rn(f[2*pq]);
            __half h1 = __float2half_rn(f[2*pq+1]);
            __half l0 = __float2half_rn(f[2*pq]   - __half2float(h0));
            __half l1 = __float2half_rn(f[2*pq+1] - __half2float(h1));
            hu[pq] = pk2h(h0, h1); lu[pq] = pk2h(l0, l1);
        }
        size_t off = row * SS_ + w * 128 + lane * 4;
        *(uint2*)(wh + off) = make_uint2(hu[0], hu[1]);
        *(uint2*)(wl + off) = make_uint2(lu[0], lu[1]);
    }
}

// ===========================================================================
// Context GEMM (fp16 2-term: [w_fh|w_fl] @ B_f, K=1024, 32 chunks of 32)
// mode 0 (content): grid(4 it, 128 bh): g_ctx  = acc
// mode 1 (edge):    grid(512 i):        g_ctx2 = acc (pure write)
// ===========================================================================
#define CT_A_TILEB (128 * LDS_ * 2)
#define CT_B_TILEB (64 * LDS_ * 2)
#define CT_STAGE   (CT_A_TILEB + CT_B_TILEB)

__global__ __launch_bounds__(256) void k_ctx(int mode)
{
    __shared__ __align__(16) char smem[2 * CT_STAGE];
    const int tid = threadIdx.x, wid = tid >> 5, lane = tid & 31;
    const int wm = wid >> 1, wn = wid & 1;

    const __half *A0, *A1, *B0;
    size_t rsA;
    int i0 = 0, bh = 0, iE = 0;
    if (mode == 0) {
        bh = blockIdx.y; i0 = blockIdx.x * 128;
        A0 = wh + (size_t)bh * SS_ * SS_ + (size_t)i0 * SS_;
        A1 = wl + (size_t)bh * SS_ * SS_ + (size_t)i0 * SS_;
        B0 = vth + (size_t)bh * DKV * SS_;
        rsA = SS_;
    } else {
        iE = blockIdx.x;
        A0 = wh + (size_t)iE * SS_;
        A1 = wl + (size_t)iE * SS_;
        B0 = evth + (size_t)iE * DKV * SS_;
        rsA = (size_t)SS_ * SS_;
    }
    const __half* At[2] = {A0, A1};

    const uint32_t sbase = s2u(smem);
    const int arow = tid >> 1, aseg = (tid & 1) << 4;
    const int brow = tid >> 2, bseg = (tid & 3) << 3;

    float acc[2][4][4];
#pragma unroll
    for (int i = 0; i < 2; i++)
#pragma unroll
        for (int j = 0; j < 4; j++)
#pragma unroll
            for (int q = 0; q < 4; q++) acc[i][j][q] = 0.f;

    {
        uint32_t dA = sbase, dB = sbase + CT_A_TILEB;
        CP_ASYNC16(dA + (arow * LDS_ + aseg) * 2,     At[0] + (size_t)arow * rsA + aseg);
        CP_ASYNC16(dA + (arow * LDS_ + aseg + 8) * 2, At[0] + (size_t)arow * rsA + aseg + 8);
        CP_ASYNC16(dB + (brow * LDS_ + bseg) * 2,     B0 + (size_t)brow * SS_ + bseg);
        CP_COMMIT();
    }

    for (int c = 0; c < 32; c++) {
        CP_WAIT0();
        __syncthreads();

        if (c + 1 < 32) {
            int t2 = (c + 1) >> 4, ko2 = ((c + 1) & 15) * 32;
            uint32_t dA = sbase + ((c + 1) & 1) * CT_STAGE;
            uint32_t dB = dA + CT_A_TILEB;
            CP_ASYNC16(dA + (arow * LDS_ + aseg) * 2,     At[t2] + (size_t)arow * rsA + ko2 + aseg);
            CP_ASYNC16(dA + (arow * LDS_ + aseg + 8) * 2, At[t2] + (size_t)arow * rsA + ko2 + aseg + 8);
            CP_ASYNC16(dB + (brow * LDS_ + bseg) * 2,     B0 + (size_t)brow * SS_ + ko2 + bseg);
            CP_COMMIT();
        }

        const uint32_t bufA = sbase + (c & 1) * CT_STAGE;
        const uint32_t bufB = bufA + CT_A_TILEB;
        const int lr = lane & 15, lc = (lane >> 4) << 3;

#pragma unroll
        for (int ks = 0; ks < 2; ks++) {
            uint32_t a[2][4];
#pragma unroll
            for (int mi = 0; mi < 2; mi++) {
                uint32_t addr = bufA + ((wm * 32 + mi * 16 + lr) * LDS_ + ks * 16 + lc) * 2;
                LDMATX4(a[mi][0], a[mi][1], a[mi][2], a[mi][3], addr);
            }
            uint32_t b[4][2];
#pragma unroll
            for (int ni2 = 0; ni2 < 2; ni2++) {
                uint32_t r0, r1, r2, r3;
                uint32_t addr = bufB + ((wn * 32 + ni2 * 16 + lr) * LDS_ + ks * 16 + lc) * 2;
                LDMATX4(r0, r1, r2, r3, addr);
                b[2 * ni2][0] = r0;     b[2 * ni2][1] = r2;
                b[2 * ni2 + 1][0] = r1; b[2 * ni2 + 1][1] = r3;
            }
#pragma unroll
            for (int mi = 0; mi < 2; mi++)
#pragma unroll
                for (int ni = 0; ni < 4; ni++)
                    MMA16816H(acc[mi][ni], a[mi], b[ni]);
        }
        __syncthreads();
    }

    const int g = lane >> 2, tc = (lane & 3) << 1;
#pragma unroll
    for (int mi = 0; mi < 2; mi++) {
        int m = wm * 32 + mi * 16 + g;
#pragma unroll
        for (int ni = 0; ni < 4; ni++) {
            int ncol = wn * 32 + ni * 8 + tc;
            if (mode == 0) {
                int i = i0 + m;
                size_t a0 = ((size_t)(bh >> 4) * SS_ + i) * DM + (bh & 15) * DKV + ncol;
                size_t a1 = a0 + (size_t)8 * DM;
                *(float2*)(g_ctx + a0) = make_float2(acc[mi][ni][0], acc[mi][ni][1]);
                *(float2*)(g_ctx + a1) = make_float2(acc[mi][ni][2], acc[mi][ni][3]);
            } else {
                int bh0 = m, bh1 = m + 8;
                size_t a0 = ((size_t)(bh0 >> 4) * SS_ + iE) * DM + (bh0 & 15) * DKV + ncol;
                size_t a1 = ((size_t)(bh1 >> 4) * SS_ + iE) * DM + (bh1 & 15) * DKV + ncol;
                *(float2*)(g_ctx2 + a0) = make_float2(acc[mi][ni][0], acc[mi][ni][1]);
                *(float2*)(g_ctx2 + a1) = make_float2(acc[mi][ni][2], acc[mi][ni][3]);
            }
        }
    }
}

// ===========================================================================
// Launcher — R7 topology: edge splits ∥ projections; content ∥ edge pairs.
// ===========================================================================
extern "C" void kernel_launch(void* const* d_in, const int* in_sizes, int n_in,
                              void* d_out, int out_size)
{
    const float* queries     = (const float*)d_in[0];
    const float* edges_key   = (const float*)d_in[1];
    const float* edges_value = (const float*)d_in[2];
    const float* attn_bias   = (const float*)d_in[3];
    const float* Wq = (const float*)d_in[4];
    const float* bq = (const float*)d_in[5];
    const float* Wk = (const float*)d_in[6];
    const float* bk = (const float*)d_in[7];
    const float* Wv = (const float*)d_in[8];
    const float* bv = (const float*)d_in[9];
    const float* Wo = (const float*)d_in[10];
    const float* bo = (const float*)d_in[11];
    float* out = (float*)d_out;

    static cudaStream_t s2 = nullptr, s3 = nullptr;
    static cudaEvent_t evFork = nullptr, evEdgeSplit = nullptr, evQKV = nullptr,
                       evEdgeSc = nullptr, evSM = nullptr, evCtx1 = nullptr;
    if (!s2) {
        cudaStreamCreateWithFlags(&s2, cudaStreamNonBlocking);
        cudaStreamCreateWithFlags(&s3, cudaStreamNonBlocking);
        cudaEventCreateWithFlags(&evFork,      cudaEventDisableTiming);
        cudaEventCreateWithFlags(&evEdgeSplit, cudaEventDisableTiming);
        cudaEventCreateWithFlags(&evQKV,       cudaEventDisableTiming);
        cudaEventCreateWithFlags(&evEdgeSc,    cudaEventDisableTiming);
        cudaEventCreateWithFlags(&evSM,        cudaEventDisableTiming);
        cudaEventCreateWithFlags(&evCtx1,      cudaEventDisableTiming);
    }

    cudaStream_t st = 0;
    cudaStreamCaptureStatus cs = cudaStreamCaptureStatusNone;
    if (cudaStreamIsCapturing(cudaStreamPerThread, &cs) == cudaSuccess &&
        cs == cudaStreamCaptureStatusActive)
        st = cudaStreamPerThread;

    // fork: edge-tensor converts overlap the projection path
    cudaEventRecord(evFork, st);
    cudaStreamWaitEvent(s2, evFork, 0);
    k_split_ek <<<8192, 256, 0, s2>>>(edges_key);
    k_split_evt<<<dim3(16, 2, 512), 256, 0, s2>>>(edges_value);
    cudaEventRecord(evEdgeSplit, s2);

    // projection path (main stream) — fp16 2-term
    k_split <<<2048, 256, 0, st>>>(queries, 0);
    k_wsplit<<<dim3(4, 128, 4), 256, 0, st>>>(Wq, Wk, Wv, Wo);
    k_gemm_f16<<<dim3(24, 32), 256, 0, st>>>(bq, bk, bv, nullptr, 0);
    cudaEventRecord(evQKV, st);

    // content scores (st) ∥ edge scores (s3, independent buffer g_sc2)
    cudaStreamWaitEvent(s3, evQKV, 0);
    cudaStreamWaitEvent(s3, evEdgeSplit, 0);
    k_scores<<<dim3(4, 512), 256, 0, s3>>>(nullptr, 1);
    cudaEventRecord(evEdgeSc, s3);

    k_scores<<<dim3(4, 4, 128), 256, 0, st>>>(attn_bias, 0);

    // softmax needs both score buffers
    cudaStreamWaitEvent(st, evEdgeSc, 0);
    k_softmax_split<<<8192, 256, 0, st>>>();
    cudaEventRecord(evSM, st);

    // content context (st) ∥ edge context (s3, independent buffer g_ctx2)
    cudaStreamWaitEvent(s3, evSM, 0);
    k_ctx<<<dim3(512), 256, 0, s3>>>(1);
    cudaEventRecord(evCtx1, s3);

    k_ctx<<<dim3(4, 128), 256, 0, st>>>(0);

    // output projection (needs both context buffers) — fp16 2-term
    cudaStreamWaitEvent(st, evCtx1, 0);
    k_split<<<2048, 256, 0, st>>>(nullptr, 1);
    k_gemm_f16<<<dim3(8, 32), 256, 0, st>>>(bo, nullptr, nullptr, out, 1);
}

// round 12
// speedup vs baseline: 2.1187x; 1.6569x over previous
#include <cuda_runtime.h>
#include <cuda_fp16.h>
#include <cstdint>

// ---------------------------------------------------------------------------
// Problem constants: B=8, S=512, D_MODEL=1024, H=16, DK=DV=64, BH=128
// ---------------------------------------------------------------------------
#define BB   8
#define SS_  512
#define DM   1024
#define HH   16
#define DKV  64
#define BH   128
#define SCALE 0.125f

// ---------------------------------------------------------------------------
// Scratch (device globals)
// ---------------------------------------------------------------------------
__device__ float g_sc  [(size_t)BH * SS_ * SS_];   // content scores + bias
__device__ float g_sc2 [(size_t)BH * SS_ * SS_];   // edge scores
__device__ float g_ctx [(size_t)BB * SS_ * DM];    // content context
__device__ float g_ctx2[(size_t)BB * SS_ * DM];    // edge context

// projection staging: single fp16 everywhere
__device__ __align__(16) __half g_A   [(size_t)4096 * 1024];
__device__ __align__(16) __half g_Actx[(size_t)4096 * 1024];
__device__ __align__(16) __half g_Bqkv[(size_t)3072 * 1024];
__device__ __align__(16) __half g_Bo  [(size_t)1024 * 1024];

// attention operands, single fp16
__device__ __align__(16) __half qh [(size_t)BH * SS_ * DKV];
__device__ __align__(16) __half kh [(size_t)BH * SS_ * DKV];
__device__ __align__(16) __half vth[(size_t)BH * DKV * SS_];   // [bh,d,s]
__device__ __align__(16) __half ekh [(size_t)SS_ * SS_ * DKV]; // [i,j,d]
__device__ __align__(16) __half evth[(size_t)SS_ * DKV * SS_]; // [i,d,j]
__device__ __align__(16) __half wh [(size_t)BH * SS_ * SS_];   // [bh,i,j]

__device__ __forceinline__ uint32_t s2u(const void* p) {
    uint32_t a;
    asm("{ .reg .u64 t; cvta.to.shared.u64 t, %1; cvt.u32.u64 %0, t; }"
        : "=r"(a) : "l"(p));
    return a;
}
__device__ __forceinline__ uint32_t pk2h(__half a, __half b) {
    return (uint32_t)__half_as_ushort(a) | ((uint32_t)__half_as_ushort(b) << 16);
}

#define CP_ASYNC16(dst, src) \
    asm volatile("cp.async.cg.shared.global [%0], [%1], 16;" :: "r"(dst), "l"(src) : "memory")
#define CP_COMMIT() asm volatile("cp.async.commit_group;" ::: "memory")
#define CP_WAIT0()  asm volatile("cp.async.wait_group 0;" ::: "memory")

#define LDMATX4(r0, r1, r2, r3, addr) \
    asm volatile("ldmatrix.sync.aligned.m8n8.x4.shared.b16 {%0,%1,%2,%3}, [%4];" \
        : "=r"(r0), "=r"(r1), "=r"(r2), "=r"(r3) : "r"(addr))

#define MMA16816H(c, a, b) \
    asm volatile("mma.sync.aligned.m16n8k16.row.col.f32.f16.f16.f32 " \
        "{%0,%1,%2,%3}, {%4,%5,%6,%7}, {%8,%9}, {%0,%1,%2,%3};" \
        : "+f"((c)[0]), "+f"((c)[1]), "+f"((c)[2]), "+f"((c)[3]) \
        : "r"((a)[0]), "r"((a)[1]), "r"((a)[2]), "r"((a)[3]), \
          "r"((b)[0]), "r"((b)[1]))

#define LDS_   40                 // padded row stride in 16-bit elems (80 bytes)
#define TILEB  (128 * LDS_ * 2)   // 10240 bytes

// ===========================================================================
// fp16 convert: fp32 [4096,1024] -> fp16 [4096,1024]
// which=0: queries -> g_A ; which=1: g_ctx+g_ctx2 -> g_Actx
// ===========================================================================
__global__ __launch_bounds__(256) void k_split(const float* __restrict__ src_in, int which)
{
    int idx = blockIdx.x * 256 + threadIdx.x;
    int r = idx >> 7;
    int c0 = (idx & 127) << 3;
    float f[8];
    if (which == 0) {
        const float* s = src_in + (size_t)r * 1024 + c0;
        float4 v0 = *(const float4*)(s);
        float4 v1 = *(const float4*)(s + 4);
        f[0]=v0.x; f[1]=v0.y; f[2]=v0.z; f[3]=v0.w;
        f[4]=v1.x; f[5]=v1.y; f[6]=v1.z; f[7]=v1.w;
    } else {
        const float* s0 = (const float*)g_ctx  + (size_t)r * 1024 + c0;
        const float* s1 = (const float*)g_ctx2 + (size_t)r * 1024 + c0;
        float4 a0 = *(const float4*)(s0), a1 = *(const float4*)(s0 + 4);
        float4 b0 = *(const float4*)(s1), b1 = *(const float4*)(s1 + 4);
        f[0]=a0.x+b0.x; f[1]=a0.y+b0.y; f[2]=a0.z+b0.z; f[3]=a0.w+b0.w;
        f[4]=a1.x+b1.x; f[5]=a1.y+b1.y; f[6]=a1.z+b1.z; f[7]=a1.w+b1.w;
    }
    __half* dst = which ? g_Actx : g_A;
    uint32_t hu[4];
#pragma unroll
    for (int i = 0; i < 4; i++)
        hu[i] = pk2h(__float2half_rn(f[2*i]), __float2half_rn(f[2*i+1]));
    uint4 H; H.x = hu[0]; H.y = hu[1]; H.z = hu[2]; H.w = hu[3];
    *(uint4*)(dst + (size_t)r * 1024 + c0) = H;
}

// ===========================================================================
// Weight fp16 transpose (4 weights): W[1024k,1024n] -> Bf[n][1024] fp16
// ===========================================================================
__global__ __launch_bounds__(256) void k_wsplit(
    const float* __restrict__ W0, const float* __restrict__ W1,
    const float* __restrict__ W2, const float* __restrict__ W3)
{
    const int slot = blockIdx.z;
    const float* W = (slot == 0) ? W0 : (slot == 1) ? W1 : (slot == 2) ? W2 : W3;
    __half* dst = (slot < 3) ? (g_Bqkv + (size_t)slot * 1024 * 1024) : g_Bo;
    int nl = blockIdx.x * 256 + threadIdx.x;
    int k0 = blockIdx.y << 3;
    uint32_t hu[4];
#pragma unroll
    for (int i = 0; i < 4; i++) {
        __half h0 = __float2half_rn(W[(size_t)(k0 + 2*i)     * 1024 + nl]);
        __half h1 = __float2half_rn(W[(size_t)(k0 + 2*i + 1) * 1024 + nl]);
        hu[i] = pk2h(h0, h1);
    }
    uint4 H; H.x = hu[0]; H.y = hu[1]; H.z = hu[2]; H.w = hu[3];
    *(uint4*)(dst + (size_t)nl * 1024 + k0) = H;
}

// ===========================================================================
// EK convert: fp32 [i,j,64] -> ekh fp16
// ===========================================================================
__global__ __launch_bounds__(256) void k_split_ek(const float* __restrict__ EK)
{
    size_t base = ((size_t)blockIdx.x * 256 + threadIdx.x) * 8;
    float4 v0 = *(const float4*)(EK + base);
    float4 v1 = *(const float4*)(EK + base + 4);
    float f[8] = {v0.x, v0.y, v0.z, v0.w, v1.x, v1.y, v1.z, v1.w};
    uint32_t hu[4];
#pragma unroll
    for (int i = 0; i < 4; i++)
        hu[i] = pk2h(__float2half_rn(f[2*i]), __float2half_rn(f[2*i+1]));
    uint4 H; H.x = hu[0]; H.y = hu[1]; H.z = hu[2]; H.w = hu[3];
    *(uint4*)(ekh + base) = H;
}

// ===========================================================================
// EV transpose-convert: fp32 [i,j,64] -> evth fp16 [i,64,512]
// ===========================================================================
__global__ __launch_bounds__(256) void k_split_evt(const float* __restrict__ EV)
{
    __shared__ float ts[32][33];
    const int jt = blockIdx.x, dt = blockIdx.y, i = blockIdx.z;
    const int t = threadIdx.x;
    const int r = t >> 3, c0 = (t & 7) << 2;

    float4 v = *(const float4*)(EV + ((size_t)(i * SS_ + jt * 32 + r)) * DKV + dt * 32 + c0);
    ts[r][c0 + 0] = v.x; ts[r][c0 + 1] = v.y;
    ts[r][c0 + 2] = v.z; ts[r][c0 + 3] = v.w;
    __syncthreads();

    uint32_t hu[2];
#pragma unroll
    for (int p = 0; p < 2; p++)
        hu[p] = pk2h(__float2half_rn(ts[c0 + 2*p][r]), __float2half_rn(ts[c0 + 2*p + 1][r]));
    size_t off = ((size_t)i * DKV + dt * 32 + r) * SS_ + jt * 32 + c0;
    *(uint2*)(evth + off) = make_uint2(hu[0], hu[1]);
}

// ===========================================================================
// fp16 mma.sync GEMM (projections): C[4096,N] = Xf @ Wf^T, K=1024.
// 2-stage cp.async, 128x128 CTA.
// mode 0: QKV -> qh / kh / vth; mode 1: OUT -> outp
// ===========================================================================
#define KTOT   1024
#define NCHUNK 32

__global__ __launch_bounds__(256) void k_gemm_f16(
    const float* __restrict__ b0p, const float* __restrict__ b1p,
    const float* __restrict__ b2p, float* __restrict__ outp, int mode)
{
    __shared__ __align__(16) char smem[2 * 2 * TILEB];

    const int tid  = threadIdx.x;
    const int wid  = tid >> 5, lane = tid & 31;
    const int wm   = wid >> 2, wn = wid & 3;
    const int m0   = blockIdx.y * 128, n0 = blockIdx.x * 128;
    const uint32_t sbase = s2u(smem);

    const __half* __restrict__ Ag = mode ? g_Actx : g_A;
    const __half* __restrict__ Bg = mode ? g_Bo   : g_Bqkv;

    const int lrow0 = tid >> 2;
    const int lseg  = (tid & 3) << 3;

    float acc[4][4][4];
#pragma unroll
    for (int i = 0; i < 4; i++)
#pragma unroll
        for (int j = 0; j < 4; j++)
#pragma unroll
            for (int q = 0; q < 4; q++) acc[i][j][q] = 0.f;

    {
        uint32_t dA = sbase, dB = sbase + TILEB;
#pragma unroll
        for (int u = 0; u < 2; u++) {
            int row = lrow0 + u * 64;
            CP_ASYNC16(dA + (row * LDS_ + lseg) * 2, Ag + (size_t)(m0 + row) * KTOT + lseg);
            CP_ASYNC16(dB + (row * LDS_ + lseg) * 2, Bg + (size_t)(n0 + row) * 1024 + lseg);
        }
        CP_COMMIT();
    }

    for (int c = 0; c < NCHUNK; c++) {
        CP_WAIT0();
        __syncthreads();

        if (c + 1 < NCHUNK) {
            uint32_t dA = sbase + ((c + 1) & 1) * 2 * TILEB;
            uint32_t dB = dA + TILEB;
            const int koff = (c + 1) * 32 + lseg;
#pragma unroll
            for (int u = 0; u < 2; u++) {
                int row = lrow0 + u * 64;
                CP_ASYNC16(dA + (row * LDS_ + lseg) * 2, Ag + (size_t)(m0 + row) * KTOT + koff);
                CP_ASYNC16(dB + (row * LDS_ + lseg) * 2, Bg + (size_t)(n0 + row) * 1024 + koff);
            }
            CP_COMMIT();
        }

        const uint32_t bufA = sbase + (c & 1) * 2 * TILEB;
        const uint32_t bufB = bufA + TILEB;
        const int lr = lane & 15, lc = (lane >> 4) << 3;

#pragma unroll
        for (int ks = 0; ks < 2; ks++) {
            uint32_t a[4][4];
#pragma unroll
            for (int mi = 0; mi < 4; mi++) {
                uint32_t addr = bufA + ((wm * 64 + mi * 16 + lr) * LDS_ + ks * 16 + lc) * 2;
                LDMATX4(a[mi][0], a[mi][1], a[mi][2], a[mi][3], addr);
            }
            uint32_t b[4][2];
#pragma unroll
            for (int ni2 = 0; ni2 < 2; ni2++) {
                uint32_t r0, r1, r2, r3;
                uint32_t addr = bufB + ((wn * 32 + ni2 * 16 + lr) * LDS_ + ks * 16 + lc) * 2;
                LDMATX4(r0, r1, r2, r3, addr);
                b[2 * ni2][0] = r0;     b[2 * ni2][1] = r2;
                b[2 * ni2 + 1][0] = r1; b[2 * ni2 + 1][1] = r3;
            }
#pragma unroll
            for (int mi = 0; mi < 4; mi++)
#pragma unroll
                for (int ni = 0; ni < 4; ni++)
                    MMA16816H(acc[mi][ni], a[mi], b[ni]);
        }
        __syncthreads();
    }

    // -------- epilogue --------
    const int g  = lane >> 2;
    const int tc = (lane & 3) << 1;

    if (mode == 0) {
        const int proj = n0 >> 10;
        const float* bias = (proj == 0) ? b0p : (proj == 1) ? b1p : b2p;
#pragma unroll
        for (int mi = 0; mi < 4; mi++) {
            int m = m0 + wm * 64 + mi * 16 + g;
            int b_ = m >> 9, s_ = m & 511;
            int s2 = s_ + 8;
#pragma unroll
            for (int ni = 0; ni < 4; ni++) {
                int nl = (n0 & 1023) + wn * 32 + ni * 8 + tc;
                int hd = nl >> 6, d = nl & 63;
                int bh_ = b_ * HH + hd;
                __half h0 = __float2half_rn(acc[mi][ni][0] + bias[nl]);
                __half h1 = __float2half_rn(acc[mi][ni][1] + bias[nl + 1]);
                __half h2 = __float2half_rn(acc[mi][ni][2] + bias[nl]);
                __half h3 = __float2half_rn(acc[mi][ni][3] + bias[nl + 1]);
                if (proj < 2) {
                    __half* dst = (proj == 0) ? qh : kh;
                    size_t o0 = ((size_t)bh_ * SS_ + s_) * DKV + d;
                    size_t o1 = o0 + 8 * DKV;
                    *(uint32_t*)(dst + o0) = pk2h(h0, h1);
                    *(uint32_t*)(dst + o1) = pk2h(h2, h3);
                } else {
                    size_t o = (size_t)bh_ * DKV * SS_ + (size_t)d * SS_;
                    vth[o + s_]       = h0;
                    vth[o + SS_ + s_] = h1;
                    vth[o + s2]       = h2;
                    vth[o + SS_ + s2] = h3;
                }
            }
        }
    } else {
#pragma unroll
        for (int mi = 0; mi < 4; mi++) {
            int m = m0 + wm * 64 + mi * 16 + g;
#pragma unroll
            for (int ni = 0; ni < 4; ni++) {
                int ncol = n0 + wn * 32 + ni * 8 + tc;
                float2 o0 = {acc[mi][ni][0] + b0p[ncol],
                             acc[mi][ni][1] + b0p[ncol + 1]};
                float2 o1 = {acc[mi][ni][2] + b0p[ncol],
                             acc[mi][ni][3] + b0p[ncol + 1]};
                *(float2*)(outp + (size_t)m * DM + ncol) = o0;
                *(float2*)(outp + (size_t)(m + 8) * DM + ncol) = o1;
            }
        }
    }
}

// ===========================================================================
// Scores GEMM (single fp16: q @ B_f, K=64, 2 chunks of 32)
// mode 0 (content): grid(4 jt, 4 it, 128 bh): g_sc  = acc*SCALE + bias
// mode 1 (edge):    grid(4 jt, 512 i):        g_sc2 = acc*SCALE (pure write)
// ===========================================================================
__global__ __launch_bounds__(256) void k_scores(const float* __restrict__ bias, int mode)
{
    __shared__ __align__(16) char smem[2 * 2 * TILEB];
    const int tid = threadIdx.x, wid = tid >> 5, lane = tid & 31;
    const int wm = wid >> 2, wn = wid & 3;
    const int j0 = blockIdx.x * 128;

    const __half *A0, *B0;
    size_t rsA;
    int i0 = 0, bh = 0, iE = 0;
    if (mode == 0) {
        i0 = blockIdx.y * 128; bh = blockIdx.z;
        A0 = qh + ((size_t)bh * SS_ + i0) * DKV;
        B0 = kh + ((size_t)bh * SS_ + j0) * DKV;
        rsA = DKV;
    } else {
        iE = blockIdx.y;
        A0 = qh + (size_t)iE * DKV;
        B0 = ekh + ((size_t)iE * SS_ + j0) * DKV;
        rsA = (size_t)SS_ * DKV;
    }

    const uint32_t sbase = s2u(smem);
    const int lrow0 = tid >> 2, lseg = (tid & 3) << 3;

    float acc[4][4][4];
#pragma unroll
    for (int i = 0; i < 4; i++)
#pragma unroll
        for (int j = 0; j < 4; j++)
#pragma unroll
            for (int q = 0; q < 4; q++) acc[i][j][q] = 0.f;

    {
        uint32_t dA = sbase, dB = sbase + TILEB;
#pragma unroll
        for (int u = 0; u < 2; u++) {
            int row = lrow0 + u * 64;
            CP_ASYNC16(dA + (row * LDS_ + lseg) * 2, A0 + (size_t)row * rsA + lseg);
            CP_ASYNC16(dB + (row * LDS_ + lseg) * 2, B0 + (size_t)row * DKV + lseg);
        }
        CP_COMMIT();
    }

    for (int c = 0; c < 2; c++) {
        CP_WAIT0();
        __syncthreads();

        if (c + 1 < 2) {
            uint32_t dA = sbase + ((c + 1) & 1) * 2 * TILEB;
            uint32_t dB = dA + TILEB;
            const int ko2 = (c + 1) * 32;
#pragma unroll
            for (int u = 0; u < 2; u++) {
                int row = lrow0 + u * 64;
                CP_ASYNC16(dA + (row * LDS_ + lseg) * 2, A0 + (size_t)row * rsA + ko2 + lseg);
                CP_ASYNC16(dB + (row * LDS_ + lseg) * 2, B0 + (size_t)row * DKV + ko2 + lseg);
            }
            CP_COMMIT();
        }

        const uint32_t bufA = sbase + (c & 1) * 2 * TILEB;
        const uint32_t bufB = bufA + TILEB;
        const int lr = lane & 15, lc = (lane >> 4) << 3;

#pragma unroll
        for (int ks = 0; ks < 2; ks++) {
            uint32_t a[4][4];
#pragma unroll
            for (int mi = 0; mi < 4; mi++) {
                uint32_t addr = bufA + ((wm * 64 + mi * 16 + lr) * LDS_ + ks * 16 + lc) * 2;
                LDMATX4(a[mi][0], a[mi][1], a[mi][2], a[mi][3], addr);
            }
            uint32_t b[4][2];
#pragma unroll
            for (int ni2 = 0; ni2 < 2; ni2++) {
                uint32_t r0, r1, r2, r3;
                uint32_t addr = bufB + ((wn * 32 + ni2 * 16 + lr) * LDS_ + ks * 16 + lc) * 2;
                LDMATX4(r0, r1, r2, r3, addr);
                b[2 * ni2][0] = r0;     b[2 * ni2][1] = r2;
                b[2 * ni2 + 1][0] = r1; b[2 * ni2 + 1][1] = r3;
            }
#pragma unroll
            for (int mi = 0; mi < 4; mi++)
#pragma unroll
                for (int ni = 0; ni < 4; ni++)
                    MMA16816H(acc[mi][ni], a[mi], b[ni]);
        }
        __syncthreads();
    }

    const int g = lane >> 2, tc = (lane & 3) << 1;
#pragma unroll
    for (int mi = 0; mi < 4; mi++) {
        int m = wm * 64 + mi * 16 + g;
#pragma unroll
        for (int ni = 0; ni < 4; ni++) {
            int jc = j0 + wn * 32 + ni * 8 + tc;
            if (mode == 0) {
                size_t base0 = ((size_t)bh * SS_ + (i0 + m)) * SS_ + jc;
                size_t base1 = base0 + 8 * SS_;
                float2 o0 = {acc[mi][ni][0] * SCALE + bias[base0],
                             acc[mi][ni][1] * SCALE + bias[base0 + 1]};
                float2 o1 = {acc[mi][ni][2] * SCALE + bias[base1],
                             acc[mi][ni][3] * SCALE + bias[base1 + 1]};
                *(float2*)(g_sc + base0) = o0;
                *(float2*)(g_sc + base1) = o1;
            } else {
                size_t base0 = ((size_t)m * SS_ + iE) * SS_ + jc;
                size_t base1 = base0 + (size_t)8 * SS_ * SS_;
                float2 o0 = {acc[mi][ni][0] * SCALE, acc[mi][ni][1] * SCALE};
                float2 o1 = {acc[mi][ni][2] * SCALE, acc[mi][ni][3] * SCALE};
                *(float2*)(g_sc2 + base0) = o0;
                *(float2*)(g_sc2 + base1) = o1;
            }
        }
    }
}

// ===========================================================================
// Softmax: read g_sc + g_sc2, softmax, write wh fp16 (single)
// ===========================================================================
__global__ __launch_bounds__(256) void k_softmax_split()
{
    const int warp = threadIdx.x >> 5, lane = threadIdx.x & 31;
    const size_t row = (size_t)blockIdx.x * 8 + warp;
    const float* p  = g_sc  + row * SS_;
    const float* p2 = g_sc2 + row * SS_;

    float4 v[4];
    float mx = -1e30f;
#pragma unroll
    for (int w = 0; w < 4; w++) {
        float4 a = *(const float4*)(p  + w * 128 + lane * 4);
        float4 b = *(const float4*)(p2 + w * 128 + lane * 4);
        v[w].x = a.x + b.x; v[w].y = a.y + b.y;
        v[w].z = a.z + b.z; v[w].w = a.w + b.w;
        mx = fmaxf(mx, fmaxf(fmaxf(v[w].x, v[w].y), fmaxf(v[w].z, v[w].w)));
    }
#pragma unroll
    for (int o = 16; o > 0; o >>= 1) mx = fmaxf(mx, __shfl_xor_sync(~0u, mx, o));

    float sum = 0.f;
#pragma unroll
    for (int w = 0; w < 4; w++) {
        v[w].x = __expf(v[w].x - mx); v[w].y = __expf(v[w].y - mx);
        v[w].z = __expf(v[w].z - mx); v[w].w = __expf(v[w].w - mx);
        sum += v[w].x + v[w].y + v[w].z + v[w].w;
    }
#pragma unroll
    for (int o = 16; o > 0; o >>= 1) sum += __shfl_xor_sync(~0u, sum, o);
    float r = 1.f / sum;
#pragma unroll
    for (int w = 0; w < 4; w++) {
        float f[4] = {v[w].x * r, v[w].y * r, v[w].z * r, v[w].w * r};
        uint32_t hu[2];
        hu[0] = pk2h(__float2half_rn(f[0]), __float2half_rn(f[1]));
        hu[1] = pk2h(__float2half_rn(f[2]), __float2half_rn(f[3]));
        size_t off = row * SS_ + w * 128 + lane * 4;
        *(uint2*)(wh + off) = make_uint2(hu[0], hu[1]);
    }
}

// ===========================================================================
// Context GEMM (single fp16: w @ B_f, K=512, 16 chunks of 32)
// mode 0 (content): grid(4 it, 128 bh): g_ctx  = acc
// mode 1 (edge):    grid(512 i):        g_ctx2 = acc (pure write)
// ===========================================================================
#define CT_A_TILEB (128 * LDS_ * 2)
#define CT_B_TILEB (64 * LDS_ * 2)
#define CT_STAGE   (CT_A_TILEB + CT_B_TILEB)

__global__ __launch_bounds__(256) void k_ctx(int mode)
{
    __shared__ __align__(16) char smem[2 * CT_STAGE];
    const int tid = threadIdx.x, wid = tid >> 5, lane = tid & 31;
    const int wm = wid >> 1, wn = wid & 1;

    const __half *A0, *B0;
    size_t rsA;
    int i0 = 0, bh = 0, iE = 0;
    if (mode == 0) {
        bh = blockIdx.y; i0 = blockIdx.x * 128;
        A0 = wh + (size_t)bh * SS_ * SS_ + (size_t)i0 * SS_;
        B0 = vth + (size_t)bh * DKV * SS_;
        rsA = SS_;
    } else {
        iE = blockIdx.x;
        A0 = wh + (size_t)iE * SS_;
        B0 = evth + (size_t)iE * DKV * SS_;
        rsA = (size_t)SS_ * SS_;
    }

    const uint32_t sbase = s2u(smem);
    const int arow = tid >> 1, aseg = (tid & 1) << 4;
    const int brow = tid >> 2, bseg = (tid & 3) << 3;

    float acc[2][4][4];
#pragma unroll
    for (int i = 0; i < 2; i++)
#pragma unroll
        for (int j = 0; j < 4; j++)
#pragma unroll
            for (int q = 0; q < 4; q++) acc[i][j][q] = 0.f;

    {
        uint32_t dA = sbase, dB = sbase + CT_A_TILEB;
        CP_ASYNC16(dA + (arow * LDS_ + aseg) * 2,     A0 + (size_t)arow * rsA + aseg);
        CP_ASYNC16(dA + (arow * LDS_ + aseg + 8) * 2, A0 + (size_t)arow * rsA + aseg + 8);
        CP_ASYNC16(dB + (brow * LDS_ + bseg) * 2,     B0 + (size_t)brow * SS_ + bseg);
        CP_COMMIT();
    }

    for (int c = 0; c < 16; c++) {
        CP_WAIT0();
        __syncthreads();

        if (c + 1 < 16) {
            int ko2 = (c + 1) * 32;
            uint32_t dA = sbase + ((c + 1) & 1) * CT_STAGE;
            uint32_t dB = dA + CT_A_TILEB;
            CP_ASYNC16(dA + (arow * LDS_ + aseg) * 2,     A0 + (size_t)arow * rsA + ko2 + aseg);
            CP_ASYNC16(dA + (arow * LDS_ + aseg + 8) * 2, A0 + (size_t)arow * rsA + ko2 + aseg + 8);
            CP_ASYNC16(dB + (brow * LDS_ + bseg) * 2,     B0 + (size_t)brow * SS_ + ko2 + bseg);
            CP_COMMIT();
        }

        const uint32_t bufA = sbase + (c & 1) * CT_STAGE;
        const uint32_t bufB = bufA + CT_A_TILEB;
        const int lr = lane & 15, lc = (lane >> 4) << 3;

#pragma unroll
        for (int ks = 0; ks < 2; ks++) {
            uint32_t a[2][4];
#pragma unroll
            for (int mi = 0; mi < 2; mi++) {
                uint32_t addr = bufA + ((wm * 32 + mi * 16 + lr) * LDS_ + ks * 16 + lc) * 2;
                LDMATX4(a[mi][0], a[mi][1], a[mi][2], a[mi][3], addr);
            }
            uint32_t b[4][2];
#pragma unroll
            for (int ni2 = 0; ni2 < 2; ni2++) {
                uint32_t r0, r1, r2, r3;
                uint32_t addr = bufB + ((wn * 32 + ni2 * 16 + lr) * LDS_ + ks * 16 + lc) * 2;
                LDMATX4(r0, r1, r2, r3, addr);
                b[2 * ni2][0] = r0;     b[2 * ni2][1] = r2;
                b[2 * ni2 + 1][0] = r1; b[2 * ni2 + 1][1] = r3;
            }
#pragma unroll
            for (int mi = 0; mi < 2; mi++)
#pragma unroll
                for (int ni = 0; ni < 4; ni++)
                    MMA16816H(acc[mi][ni], a[mi], b[ni]);
        }
        __syncthreads();
    }

    const int g = lane >> 2, tc = (lane & 3) << 1;
#pragma unroll
    for (int mi = 0; mi < 2; mi++) {
        int m = wm * 32 + mi * 16 + g;
#pragma unroll
        for (int ni = 0; ni < 4; ni++) {
            int ncol = wn * 32 + ni * 8 + tc;
            if (mode == 0) {
                int i = i0 + m;
                size_t a0 = ((size_t)(bh >> 4) * SS_ + i) * DM + (bh & 15) * DKV + ncol;
                size_t a1 = a0 + (size_t)8 * DM;
                *(float2*)(g_ctx + a0) = make_float2(acc[mi][ni][0], acc[mi][ni][1]);
                *(float2*)(g_ctx + a1) = make_float2(acc[mi][ni][2], acc[mi][ni][3]);
            } else {
                int bh0 = m, bh1 = m + 8;
                size_t a0 = ((size_t)(bh0 >> 4) * SS_ + iE) * DM + (bh0 & 15) * DKV + ncol;
                size_t a1 = ((size_t)(bh1 >> 4) * SS_ + iE) * DM + (bh1 & 15) * DKV + ncol;
                *(float2*)(g_ctx2 + a0) = make_float2(acc[mi][ni][0], acc[mi][ni][1]);
                *(float2*)(g_ctx2 + a1) = make_float2(acc[mi][ni][2], acc[mi][ni][3]);
            }
        }
    }
}

// ===========================================================================
// Launcher — R7 topology: edge converts ∥ projections; content ∥ edge pairs.
// ===========================================================================
extern "C" void kernel_launch(void* const* d_in, const int* in_sizes, int n_in,
                              void* d_out, int out_size)
{
    const float* queries     = (const float*)d_in[0];
    const float* edges_key   = (const float*)d_in[1];
    const float* edges_value = (const float*)d_in[2];
    const float* attn_bias   = (const float*)d_in[3];
    const float* Wq = (const float*)d_in[4];
    const float* bq = (const float*)d_in[5];
    const float* Wk = (const float*)d_in[6];
    const float* bk = (const float*)d_in[7];
    const float* Wv = (const float*)d_in[8];
    const float* bv = (const float*)d_in[9];
    const float* Wo = (const float*)d_in[10];
    const float* bo = (const float*)d_in[11];
    float* out = (float*)d_out;

    static cudaStream_t s2 = nullptr, s3 = nullptr;
    static cudaEvent_t evFork = nullptr, evEdgeSplit = nullptr, evQKV = nullptr,
                       evEdgeSc = nullptr, evSM = nullptr, evCtx1 = nullptr;
    if (!s2) {
        cudaStreamCreateWithFlags(&s2, cudaStreamNonBlocking);
        cudaStreamCreateWithFlags(&s3, cudaStreamNonBlocking);
        cudaEventCreateWithFlags(&evFork,      cudaEventDisableTiming);
        cudaEventCreateWithFlags(&evEdgeSplit, cudaEventDisableTiming);
        cudaEventCreateWithFlags(&evQKV,       cudaEventDisableTiming);
        cudaEventCreateWithFlags(&evEdgeSc,    cudaEventDisableTiming);
        cudaEventCreateWithFlags(&evSM,        cudaEventDisableTiming);
        cudaEventCreateWithFlags(&evCtx1,      cudaEventDisableTiming);
    }

    cudaStream_t st = 0;
    cudaStreamCaptureStatus cs = cudaStreamCaptureStatusNone;
    if (cudaStreamIsCapturing(cudaStreamPerThread, &cs) == cudaSuccess &&
        cs == cudaStreamCaptureStatusActive)
        st = cudaStreamPerThread;

    // fork: edge-tensor converts overlap the projection path
    cudaEventRecord(evFork, st);
    cudaStreamWaitEvent(s2, evFork, 0);
    k_split_ek <<<8192, 256, 0, s2>>>(edges_key);
    k_split_evt<<<dim3(16, 2, 512), 256, 0, s2>>>(edges_value);
    cudaEventRecord(evEdgeSplit, s2);

    // projection path (main stream) — single fp16, K=1024
    k_split <<<2048, 256, 0, st>>>(queries, 0);
    k_wsplit<<<dim3(4, 128, 4), 256, 0, st>>>(Wq, Wk, Wv, Wo);
    k_gemm_f16<<<dim3(24, 32), 256, 0, st>>>(bq, bk, bv, nullptr, 0);
    cudaEventRecord(evQKV, st);

    // content scores (st) ∥ edge scores (s3, independent buffer g_sc2)
    cudaStreamWaitEvent(s3, evQKV, 0);
    cudaStreamWaitEvent(s3, evEdgeSplit, 0);
    k_scores<<<dim3(4, 512), 256, 0, s3>>>(nullptr, 1);
    cudaEventRecord(evEdgeSc, s3);

    k_scores<<<dim3(4, 4, 128), 256, 0, st>>>(attn_bias, 0);

    // softmax needs both score buffers
    cudaStreamWaitEvent(st, evEdgeSc, 0);
    k_softmax_split<<<8192, 256, 0, st>>>();
    cudaEventRecord(evSM, st);

    // content context (st) ∥ edge context (s3, independent buffer g_ctx2)
    cudaStreamWaitEvent(s3, evSM, 0);
    k_ctx<<<dim3(512), 256, 0, s3>>>(1);
    cudaEventRecord(evCtx1, s3);

    k_ctx<<<dim3(4, 128), 256, 0, st>>>(0);

    // output projection (needs both context buffers) — single fp16, K=1024
    cudaStreamWaitEvent(st, evCtx1, 0);
    k_split<<<2048, 256, 0, st>>>(nullptr, 1);
    k_gemm_f16<<<dim3(8, 32), 256, 0, st>>>(bo, nullptr, nullptr, out, 1);
}

// round 13
// speedup vs baseline: 2.2844x; 1.0782x over previous
#include <cuda_runtime.h>
#include <cuda_fp16.h>
#include <cstdint>

// ---------------------------------------------------------------------------
// Problem constants: B=8, S=512, D_MODEL=1024, H=16, DK=DV=64, BH=128
// ---------------------------------------------------------------------------
#define BB   8
#define SS_  512
#define DM   1024
#define HH   16
#define DKV  64
#define BH   128
#define SCALE 0.125f

// ---------------------------------------------------------------------------
// Scratch (device globals)
// ---------------------------------------------------------------------------
__device__ __align__(16) __half g_sch [(size_t)BH * SS_ * SS_];  // content comp (fp16)
__device__ __align__(16) __half g_sc2h[(size_t)BH * SS_ * SS_];  // edge comp (fp16)
__device__ float g_ctx [(size_t)BB * SS_ * DM];    // content context
__device__ float g_ctx2[(size_t)BB * SS_ * DM];    // edge context

// projection staging: single fp16 everywhere
__device__ __align__(16) __half g_A   [(size_t)4096 * 1024];
__device__ __align__(16) __half g_Actx[(size_t)4096 * 1024];
__device__ __align__(16) __half g_Bqkv[(size_t)3072 * 1024];
__device__ __align__(16) __half g_Bo  [(size_t)1024 * 1024];

// attention operands, single fp16
__device__ __align__(16) __half qh [(size_t)BH * SS_ * DKV];
__device__ __align__(16) __half kh [(size_t)BH * SS_ * DKV];
__device__ __align__(16) __half vth[(size_t)BH * DKV * SS_];   // [bh,d,s]
__device__ __align__(16) __half ekh [(size_t)SS_ * SS_ * DKV]; // [i,j,d]
__device__ __align__(16) __half evth[(size_t)SS_ * DKV * SS_]; // [i,d,j]
__device__ __align__(16) __half wh [(size_t)BH * SS_ * SS_];   // [bh,i,j]

__device__ __forceinline__ uint32_t s2u(const void* p) {
    uint32_t a;
    asm("{ .reg .u64 t; cvta.to.shared.u64 t, %1; cvt.u32.u64 %0, t; }"
        : "=r"(a) : "l"(p));
    return a;
}
__device__ __forceinline__ uint32_t pk2h(__half a, __half b) {
    return (uint32_t)__half_as_ushort(a) | ((uint32_t)__half_as_ushort(b) << 16);
}

#define CP_ASYNC16(dst, src) \
    asm volatile("cp.async.cg.shared.global [%0], [%1], 16;" :: "r"(dst), "l"(src) : "memory")
#define CP_COMMIT() asm volatile("cp.async.commit_group;" ::: "memory")
#define CP_WAIT0()  asm volatile("cp.async.wait_group 0;" ::: "memory")

#define LDMATX4(r0, r1, r2, r3, addr) \
    asm volatile("ldmatrix.sync.aligned.m8n8.x4.shared.b16 {%0,%1,%2,%3}, [%4];" \
        : "=r"(r0), "=r"(r1), "=r"(r2), "=r"(r3) : "r"(addr))

#define MMA16816H(c, a, b) \
    asm volatile("mma.sync.aligned.m16n8k16.row.col.f32.f16.f16.f32 " \
        "{%0,%1,%2,%3}, {%4,%5,%6,%7}, {%8,%9}, {%0,%1,%2,%3};" \
        : "+f"((c)[0]), "+f"((c)[1]), "+f"((c)[2]), "+f"((c)[3]) \
        : "r"((a)[0]), "r"((a)[1]), "r"((a)[2]), "r"((a)[3]), \
          "r"((b)[0]), "r"((b)[1]))

#define LDS_   40                 // padded row stride in 16-bit elems (80 bytes)
#define TILEB  (128 * LDS_ * 2)   // 10240 bytes

// ===========================================================================
// fp16 convert: fp32 [4096,1024] -> fp16 [4096,1024]
// which=0: queries -> g_A ; which=1: g_ctx+g_ctx2 -> g_Actx
// ===========================================================================
__global__ __launch_bounds__(256) void k_split(const float* __restrict__ src_in, int which)
{
    int idx = blockIdx.x * 256 + threadIdx.x;
    int r = idx >> 7;
    int c0 = (idx & 127) << 3;
    float f[8];
    if (which == 0) {
        const float* s = src_in + (size_t)r * 1024 + c0;
        float4 v0 = *(const float4*)(s);
        float4 v1 = *(const float4*)(s + 4);
        f[0]=v0.x; f[1]=v0.y; f[2]=v0.z; f[3]=v0.w;
        f[4]=v1.x; f[5]=v1.y; f[6]=v1.z; f[7]=v1.w;
    } else {
        const float* s0 = (const float*)g_ctx  + (size_t)r * 1024 + c0;
        const float* s1 = (const float*)g_ctx2 + (size_t)r * 1024 + c0;
        float4 a0 = *(const float4*)(s0), a1 = *(const float4*)(s0 + 4);
        float4 b0 = *(const float4*)(s1), b1 = *(const float4*)(s1 + 4);
        f[0]=a0.x+b0.x; f[1]=a0.y+b0.y; f[2]=a0.z+b0.z; f[3]=a0.w+b0.w;
        f[4]=a1.x+b1.x; f[5]=a1.y+b1.y; f[6]=a1.z+b1.z; f[7]=a1.w+b1.w;
    }
    __half* dst = which ? g_Actx : g_A;
    uint32_t hu[4];
#pragma unroll
    for (int i = 0; i < 4; i++)
        hu[i] = pk2h(__float2half_rn(f[2*i]), __float2half_rn(f[2*i+1]));
    uint4 H; H.x = hu[0]; H.y = hu[1]; H.z = hu[2]; H.w = hu[3];
    *(uint4*)(dst + (size_t)r * 1024 + c0) = H;
}

// ===========================================================================
// Weight fp16 transpose (4 weights): W[1024k,1024n] -> Bf[n][1024] fp16
// ===========================================================================
__global__ __launch_bounds__(256) void k_wsplit(
    const float* __restrict__ W0, const float* __restrict__ W1,
    const float* __restrict__ W2, const float* __restrict__ W3)
{
    const int slot = blockIdx.z;
    const float* W = (slot == 0) ? W0 : (slot == 1) ? W1 : (slot == 2) ? W2 : W3;
    __half* dst = (slot < 3) ? (g_Bqkv + (size_t)slot * 1024 * 1024) : g_Bo;
    int nl = blockIdx.x * 256 + threadIdx.x;
    int k0 = blockIdx.y << 3;
    uint32_t hu[4];
#pragma unroll
    for (int i = 0; i < 4; i++) {
        __half h0 = __float2half_rn(W[(size_t)(k0 + 2*i)     * 1024 + nl]);
        __half h1 = __float2half_rn(W[(size_t)(k0 + 2*i + 1) * 1024 + nl]);
        hu[i] = pk2h(h0, h1);
    }
    uint4 H; H.x = hu[0]; H.y = hu[1]; H.z = hu[2]; H.w = hu[3];
    *(uint4*)(dst + (size_t)nl * 1024 + k0) = H;
}

// ===========================================================================
// EK convert: fp32 [i,j,64] -> ekh fp16
// ===========================================================================
__global__ __launch_bounds__(256) void k_split_ek(const float* __restrict__ EK)
{
    size_t base = ((size_t)blockIdx.x * 256 + threadIdx.x) * 8;
    float4 v0 = *(const float4*)(EK + base);
    float4 v1 = *(const float4*)(EK + base + 4);
    float f[8] = {v0.x, v0.y, v0.z, v0.w, v1.x, v1.y, v1.z, v1.w};
    uint32_t hu[4];
#pragma unroll
    for (int i = 0; i < 4; i++)
        hu[i] = pk2h(__float2half_rn(f[2*i]), __float2half_rn(f[2*i+1]));
    uint4 H; H.x = hu[0]; H.y = hu[1]; H.z = hu[2]; H.w = hu[3];
    *(uint4*)(ekh + base) = H;
}

// ===========================================================================
// EV transpose-convert: fp32 [i,j,64] -> evth fp16 [i,64,512]
// ===========================================================================
__global__ __launch_bounds__(256) void k_split_evt(const float* __restrict__ EV)
{
    __shared__ float ts[32][33];
    const int jt = blockIdx.x, dt = blockIdx.y, i = blockIdx.z;
    const int t = threadIdx.x;
    const int r = t >> 3, c0 = (t & 7) << 2;

    float4 v = *(const float4*)(EV + ((size_t)(i * SS_ + jt * 32 + r)) * DKV + dt * 32 + c0);
    ts[r][c0 + 0] = v.x; ts[r][c0 + 1] = v.y;
    ts[r][c0 + 2] = v.z; ts[r][c0 + 3] = v.w;
    __syncthreads();

    uint32_t hu[2];
#pragma unroll
    for (int p = 0; p < 2; p++)
        hu[p] = pk2h(__float2half_rn(ts[c0 + 2*p][r]), __float2half_rn(ts[c0 + 2*p + 1][r]));
    size_t off = ((size_t)i * DKV + dt * 32 + r) * SS_ + jt * 32 + c0;
    *(uint2*)(evth + off) = make_uint2(hu[0], hu[1]);
}

// ===========================================================================
// fp16 mma.sync GEMM (projections): C[4096,N] = Xf @ Wf^T, K=1024.
// 2-stage cp.async, 128x128 CTA.
// mode 0: QKV -> qh / kh / vth; mode 1: OUT -> outp
// ===========================================================================
#define KTOT   1024
#define NCHUNK 32

__global__ __launch_bounds__(256) void k_gemm_f16(
    const float* __restrict__ b0p, const float* __restrict__ b1p,
    const float* __restrict__ b2p, float* __restrict__ outp, int mode)
{
    __shared__ __align__(16) char smem[2 * 2 * TILEB];

    const int tid  = threadIdx.x;
    const int wid  = tid >> 5, lane = tid & 31;
    const int wm   = wid >> 2, wn = wid & 3;
    const int m0   = blockIdx.y * 128, n0 = blockIdx.x * 128;
    const uint32_t sbase = s2u(smem);

    const __half* __restrict__ Ag = mode ? g_Actx : g_A;
    const __half* __restrict__ Bg = mode ? g_Bo   : g_Bqkv;

    const int lrow0 = tid >> 2;
    const int lseg  = (tid & 3) << 3;

    float acc[4][4][4];
#pragma unroll
    for (int i = 0; i < 4; i++)
#pragma unroll
        for (int j = 0; j < 4; j++)
#pragma unroll
            for (int q = 0; q < 4; q++) acc[i][j][q] = 0.f;

    {
        uint32_t dA = sbase, dB = sbase + TILEB;
#pragma unroll
        for (int u = 0; u < 2; u++) {
            int row = lrow0 + u * 64;
            CP_ASYNC16(dA + (row * LDS_ + lseg) * 2, Ag + (size_t)(m0 + row) * KTOT + lseg);
            CP_ASYNC16(dB + (row * LDS_ + lseg) * 2, Bg + (size_t)(n0 + row) * 1024 + lseg);
        }
        CP_COMMIT();
    }

    for (int c = 0; c < NCHUNK; c++) {
        CP_WAIT0();
        __syncthreads();

        if (c + 1 < NCHUNK) {
            uint32_t dA = sbase + ((c + 1) & 1) * 2 * TILEB;
            uint32_t dB = dA + TILEB;
            const int koff = (c + 1) * 32 + lseg;
#pragma unroll
            for (int u = 0; u < 2; u++) {
                int row = lrow0 + u * 64;
                CP_ASYNC16(dA + (row * LDS_ + lseg) * 2, Ag + (size_t)(m0 + row) * KTOT + koff);
                CP_ASYNC16(dB + (row * LDS_ + lseg) * 2, Bg + (size_t)(n0 + row) * 1024 + koff);
            }
            CP_COMMIT();
        }

        const uint32_t bufA = sbase + (c & 1) * 2 * TILEB;
        const uint32_t bufB = bufA + TILEB;
        const int lr = lane & 15, lc = (lane >> 4) << 3;

#pragma unroll
        for (int ks = 0; ks < 2; ks++) {
            uint32_t a[4][4];
#pragma unroll
            for (int mi = 0; mi < 4; mi++) {
                uint32_t addr = bufA + ((wm * 64 + mi * 16 + lr) * LDS_ + ks * 16 + lc) * 2;
                LDMATX4(a[mi][0], a[mi][1], a[mi][2], a[mi][3], addr);
            }
            uint32_t b[4][2];
#pragma unroll
            for (int ni2 = 0; ni2 < 2; ni2++) {
                uint32_t r0, r1, r2, r3;
                uint32_t addr = bufB + ((wn * 32 + ni2 * 16 + lr) * LDS_ + ks * 16 + lc) * 2;
                LDMATX4(r0, r1, r2, r3, addr);
                b[2 * ni2][0] = r0;     b[2 * ni2][1] = r2;
                b[2 * ni2 + 1][0] = r1; b[2 * ni2 + 1][1] = r3;
            }
#pragma unroll
            for (int mi = 0; mi < 4; mi++)
#pragma unroll
                for (int ni = 0; ni < 4; ni++)
                    MMA16816H(acc[mi][ni], a[mi], b[ni]);
        }
        __syncthreads();
    }

    // -------- epilogue --------
    const int g  = lane >> 2;
    const int tc = (lane & 3) << 1;

    if (mode == 0) {
        const int proj = n0 >> 10;
        const float* bias = (proj == 0) ? b0p : (proj == 1) ? b1p : b2p;
#pragma unroll
        for (int mi = 0; mi < 4; mi++) {
            int m = m0 + wm * 64 + mi * 16 + g;
            int b_ = m >> 9, s_ = m & 511;
            int s2 = s_ + 8;
#pragma unroll
            for (int ni = 0; ni < 4; ni++) {
                int nl = (n0 & 1023) + wn * 32 + ni * 8 + tc;
                int hd = nl >> 6, d = nl & 63;
                int bh_ = b_ * HH + hd;
                __half h0 = __float2half_rn(acc[mi][ni][0] + bias[nl]);
                __half h1 = __float2half_rn(acc[mi][ni][1] + bias[nl + 1]);
                __half h2 = __float2half_rn(acc[mi][ni][2] + bias[nl]);
                __half h3 = __float2half_rn(acc[mi][ni][3] + bias[nl + 1]);
                if (proj < 2) {
                    __half* dst = (proj == 0) ? qh : kh;
                    size_t o0 = ((size_t)bh_ * SS_ + s_) * DKV + d;
                    size_t o1 = o0 + 8 * DKV;
                    *(uint32_t*)(dst + o0) = pk2h(h0, h1);
                    *(uint32_t*)(dst + o1) = pk2h(h2, h3);
                } else {
                    size_t o = (size_t)bh_ * DKV * SS_ + (size_t)d * SS_;
                    vth[o + s_]       = h0;
                    vth[o + SS_ + s_] = h1;
                    vth[o + s2]       = h2;
                    vth[o + SS_ + s2] = h3;
                }
            }
        }
    } else {
#pragma unroll
        for (int mi = 0; mi < 4; mi++) {
            int m = m0 + wm * 64 + mi * 16 + g;
#pragma unroll
            for (int ni = 0; ni < 4; ni++) {
                int ncol = n0 + wn * 32 + ni * 8 + tc;
                float2 o0 = {acc[mi][ni][0] + b0p[ncol],
                             acc[mi][ni][1] + b0p[ncol + 1]};
                float2 o1 = {acc[mi][ni][2] + b0p[ncol],
                             acc[mi][ni][3] + b0p[ncol + 1]};
                *(float2*)(outp + (size_t)m * DM + ncol) = o0;
                *(float2*)(outp + (size_t)(m + 8) * DM + ncol) = o1;
            }
        }
    }
}

// ===========================================================================
// Scores GEMM (single fp16: q @ B_f, K=64, 2 chunks of 32).
// Writes component * SCALE as fp16 (no bias here; softmax adds bias in fp32).
// mode 0 (content): grid(4 jt, 4 it, 128 bh) -> g_sch
// mode 1 (edge):    grid(4 jt, 512 i)        -> g_sc2h
// ===========================================================================
__global__ __launch_bounds__(256) void k_scores(int mode)
{
    __shared__ __align__(16) char smem[2 * 2 * TILEB];
    const int tid = threadIdx.x, wid = tid >> 5, lane = tid & 31;
    const int wm = wid >> 2, wn = wid & 3;
    const int j0 = blockIdx.x * 128;

    const __half *A0, *B0;
    size_t rsA;
    int i0 = 0, bh = 0, iE = 0;
    if (mode == 0) {
        i0 = blockIdx.y * 128; bh = blockIdx.z;
        A0 = qh + ((size_t)bh * SS_ + i0) * DKV;
        B0 = kh + ((size_t)bh * SS_ + j0) * DKV;
        rsA = DKV;
    } else {
        iE = blockIdx.y;
        A0 = qh + (size_t)iE * DKV;
        B0 = ekh + ((size_t)iE * SS_ + j0) * DKV;
        rsA = (size_t)SS_ * DKV;
    }

    const uint32_t sbase = s2u(smem);
    const int lrow0 = tid >> 2, lseg = (tid & 3) << 3;

    float acc[4][4][4];
#pragma unroll
    for (int i = 0; i < 4; i++)
#pragma unroll
        for (int j = 0; j < 4; j++)
#pragma unroll
            for (int q = 0; q < 4; q++) acc[i][j][q] = 0.f;

    {
        uint32_t dA = sbase, dB = sbase + TILEB;
#pragma unroll
        for (int u = 0; u < 2; u++) {
            int row = lrow0 + u * 64;
            CP_ASYNC16(dA + (row * LDS_ + lseg) * 2, A0 + (size_t)row * rsA + lseg);
            CP_ASYNC16(dB + (row * LDS_ + lseg) * 2, B0 + (size_t)row * DKV + lseg);
        }
        CP_COMMIT();
    }

    for (int c = 0; c < 2; c++) {
        CP_WAIT0();
        __syncthreads();

        if (c + 1 < 2) {
            uint32_t dA = sbase + ((c + 1) & 1) * 2 * TILEB;
            uint32_t dB = dA + TILEB;
            const int ko2 = (c + 1) * 32;
#pragma unroll
            for (int u = 0; u < 2; u++) {
                int row = lrow0 + u * 64;
                CP_ASYNC16(dA + (row * LDS_ + lseg) * 2, A0 + (size_t)row * rsA + ko2 + lseg);
                CP_ASYNC16(dB + (row * LDS_ + lseg) * 2, B0 + (size_t)row * DKV + ko2 + lseg);
            }
            CP_COMMIT();
        }

        const uint32_t bufA = sbase + (c & 1) * 2 * TILEB;
        const uint32_t bufB = bufA + TILEB;
        const int lr = lane & 15, lc = (lane >> 4) << 3;

#pragma unroll
        for (int ks = 0; ks < 2; ks++) {
            uint32_t a[4][4];
#pragma unroll
            for (int mi = 0; mi < 4; mi++) {
                uint32_t addr = bufA + ((wm * 64 + mi * 16 + lr) * LDS_ + ks * 16 + lc) * 2;
                LDMATX4(a[mi][0], a[mi][1], a[mi][2], a[mi][3], addr);
            }
            uint32_t b[4][2];
#pragma unroll
            for (int ni2 = 0; ni2 < 2; ni2++) {
                uint32_t r0, r1, r2, r3;
                uint32_t addr = bufB + ((wn * 32 + ni2 * 16 + lr) * LDS_ + ks * 16 + lc) * 2;
                LDMATX4(r0, r1, r2, r3, addr);
                b[2 * ni2][0] = r0;     b[2 * ni2][1] = r2;
                b[2 * ni2 + 1][0] = r1; b[2 * ni2 + 1][1] = r3;
            }
#pragma unroll
            for (int mi = 0; mi < 4; mi++)
#pragma unroll
                for (int ni = 0; ni < 4; ni++)
                    MMA16816H(acc[mi][ni], a[mi], b[ni]);
        }
        __syncthreads();
    }

    const int g = lane >> 2, tc = (lane & 3) << 1;
#pragma unroll
    for (int mi = 0; mi < 4; mi++) {
        int m = wm * 64 + mi * 16 + g;
#pragma unroll
        for (int ni = 0; ni < 4; ni++) {
            int jc = j0 + wn * 32 + ni * 8 + tc;
            uint32_t p0 = pk2h(__float2half_rn(acc[mi][ni][0] * SCALE),
                               __float2half_rn(acc[mi][ni][1] * SCALE));
            uint32_t p1 = pk2h(__float2half_rn(acc[mi][ni][2] * SCALE),
                               __float2half_rn(acc[mi][ni][3] * SCALE));
            if (mode == 0) {
                size_t base0 = ((size_t)bh * SS_ + (i0 + m)) * SS_ + jc;
                size_t base1 = base0 + 8 * SS_;
                *(uint32_t*)(g_sch + base0) = p0;
                *(uint32_t*)(g_sch + base1) = p1;
            } else {
                size_t base0 = ((size_t)m * SS_ + iE) * SS_ + jc;
                size_t base1 = base0 + (size_t)8 * SS_ * SS_;
                *(uint32_t*)(g_sc2h + base0) = p0;
                *(uint32_t*)(g_sc2h + base1) = p1;
            }
        }
    }
}

// ===========================================================================
// Softmax: read fp16 components + fp32 bias, sum in fp32, write wh fp16
// row = bh*512 + i ; bias layout [bh,i,j] matches row*512
// ===========================================================================
__global__ __launch_bounds__(256) void k_softmax_split(const float* __restrict__ bias)
{
    const int warp = threadIdx.x >> 5, lane = threadIdx.x & 31;
    const size_t row = (size_t)blockIdx.x * 8 + warp;
    const __half* p  = g_sch  + row * SS_;
    const __half* p2 = g_sc2h + row * SS_;
    const float*  pb = bias   + row * SS_;

    float4 v[4];
    float mx = -1e30f;
#pragma unroll
    for (int w = 0; w < 4; w++) {
        uint2 ua = *(const uint2*)(p  + w * 128 + lane * 4);
        uint2 ub = *(const uint2*)(p2 + w * 128 + lane * 4);
        float4 bz = *(const float4*)(pb + w * 128 + lane * 4);
        __half2 a0 = *(__half2*)&ua.x, a1 = *(__half2*)&ua.y;
        __half2 b0 = *(__half2*)&ub.x, b1 = *(__half2*)&ub.y;
        float2 fa0 = __half22float2(a0), fa1 = __half22float2(a1);
        float2 fb0 = __half22float2(b0), fb1 = __half22float2(b1);
        v[w].x = fa0.x + fb0.x + bz.x;
        v[w].y = fa0.y + fb0.y + bz.y;
        v[w].z = fa1.x + fb1.x + bz.z;
        v[w].w = fa1.y + fb1.y + bz.w;
        mx = fmaxf(mx, fmaxf(fmaxf(v[w].x, v[w].y), fmaxf(v[w].z, v[w].w)));
    }
#pragma unroll
    for (int o = 16; o > 0; o >>= 1) mx = fmaxf(mx, __shfl_xor_sync(~0u, mx, o));

    float sum = 0.f;
#pragma unroll
    for (int w = 0; w < 4; w++) {
        v[w].x = __expf(v[w].x - mx); v[w].y = __expf(v[w].y - mx);
        v[w].z = __expf(v[w].z - mx); v[w].w = __expf(v[w].w - mx);
        sum += v[w].x + v[w].y + v[w].z + v[w].w;
    }
#pragma unroll
    for (int o = 16; o > 0; o >>= 1) sum += __shfl_xor_sync(~0u, sum, o);
    float r = 1.f / sum;
#pragma unroll
    for (int w = 0; w < 4; w++) {
        float f[4] = {v[w].x * r, v[w].y * r, v[w].z * r, v[w].w * r};
        uint32_t hu[2];
        hu[0] = pk2h(__float2half_rn(f[0]), __float2half_rn(f[1]));
        hu[1] = pk2h(__float2half_rn(f[2]), __float2half_rn(f[3]));
        size_t off = row * SS_ + w * 128 + lane * 4;
        *(uint2*)(wh + off) = make_uint2(hu[0], hu[1]);
    }
}

// ===========================================================================
// Context GEMM (single fp16: w @ B_f, K=512, 16 chunks of 32)
// mode 0 (content): grid(4 it, 128 bh): g_ctx  = acc
// mode 1 (edge):    grid(512 i):        g_ctx2 = acc (pure write)
// ===========================================================================
#define CT_A_TILEB (128 * LDS_ * 2)
#define CT_B_TILEB (64 * LDS_ * 2)
#define CT_STAGE   (CT_A_TILEB + CT_B_TILEB)

__global__ __launch_bounds__(256) void k_ctx(int mode)
{
    __shared__ __align__(16) char smem[2 * CT_STAGE];
    const int tid = threadIdx.x, wid = tid >> 5, lane = tid & 31;
    const int wm = wid >> 1, wn = wid & 1;

    const __half *A0, *B0;
    size_t rsA;
    int i0 = 0, bh = 0, iE = 0;
    if (mode == 0) {
        bh = blockIdx.y; i0 = blockIdx.x * 128;
        A0 = wh + (size_t)bh * SS_ * SS_ + (size_t)i0 * SS_;
        B0 = vth + (size_t)bh * DKV * SS_;
        rsA = SS_;
    } else {
        iE = blockIdx.x;
        A0 = wh + (size_t)iE * SS_;
        B0 = evth + (size_t)iE * DKV * SS_;
        rsA = (size_t)SS_ * SS_;
    }

    const uint32_t sbase = s2u(smem);
    const int arow = tid >> 1, aseg = (tid & 1) << 4;
    const int brow = tid >> 2, bseg = (tid & 3) << 3;

    float acc[2][4][4];
#pragma unroll
    for (int i = 0; i < 2; i++)
#pragma unroll
        for (int j = 0; j < 4; j++)
#pragma unroll
            for (int q = 0; q < 4; q++) acc[i][j][q] = 0.f;

    {
        uint32_t dA = sbase, dB = sbase + CT_A_TILEB;
        CP_ASYNC16(dA + (arow * LDS_ + aseg) * 2,     A0 + (size_t)arow * rsA + aseg);
        CP_ASYNC16(dA + (arow * LDS_ + aseg + 8) * 2, A0 + (size_t)arow * rsA + aseg + 8);
        CP_ASYNC16(dB + (brow * LDS_ + bseg) * 2,     B0 + (size_t)brow * SS_ + bseg);
        CP_COMMIT();
    }

    for (int c = 0; c < 16; c++) {
        CP_WAIT0();
        __syncthreads();

        if (c + 1 < 16) {
            int ko2 = (c + 1) * 32;
            uint32_t dA = sbase + ((c + 1) & 1) * CT_STAGE;
            uint32_t dB = dA + CT_A_TILEB;
            CP_ASYNC16(dA + (arow * LDS_ + aseg) * 2,     A0 + (size_t)arow * rsA + ko2 + aseg);
            CP_ASYNC16(dA + (arow * LDS_ + aseg + 8) * 2, A0 + (size_t)arow * rsA + ko2 + aseg + 8);
            CP_ASYNC16(dB + (brow * LDS_ + bseg) * 2,     B0 + (size_t)brow * SS_ + ko2 + bseg);
            CP_COMMIT();
        }

        const uint32_t bufA = sbase + (c & 1) * CT_STAGE;
        const uint32_t bufB = bufA + CT_A_TILEB;
        const int lr = lane & 15, lc = (lane >> 4) << 3;

#pragma unroll
        for (int ks = 0; ks < 2; ks++) {
            uint32_t a[2][4];
#pragma unroll
            for (int mi = 0; mi < 2; mi++) {
                uint32_t addr = bufA + ((wm * 32 + mi * 16 + lr) * LDS_ + ks * 16 + lc) * 2;
                LDMATX4(a[mi][0], a[mi][1], a[mi][2], a[mi][3], addr);
            }
            uint32_t b[4][2];
#pragma unroll
            for (int ni2 = 0; ni2 < 2; ni2++) {
                uint32_t r0, r1, r2, r3;
                uint32_t addr = bufB + ((wn * 32 + ni2 * 16 + lr) * LDS_ + ks * 16 + lc) * 2;
                LDMATX4(r0, r1, r2, r3, addr);
                b[2 * ni2][0] = r0;     b[2 * ni2][1] = r2;
                b[2 * ni2 + 1][0] = r1; b[2 * ni2 + 1][1] = r3;
            }
#pragma unroll
            for (int mi = 0; mi < 2; mi++)
#pragma unroll
                for (int ni = 0; ni < 4; ni++)
                    MMA16816H(acc[mi][ni], a[mi], b[ni]);
        }
        __syncthreads();
    }

    const int g = lane >> 2, tc = (lane & 3) << 1;
#pragma unroll
    for (int mi = 0; mi < 2; mi++) {
        int m = wm * 32 + mi * 16 + g;
#pragma unroll
        for (int ni = 0; ni < 4; ni++) {
            int ncol = wn * 32 + ni * 8 + tc;
            if (mode == 0) {
                int i = i0 + m;
                size_t a0 = ((size_t)(bh >> 4) * SS_ + i) * DM + (bh & 15) * DKV + ncol;
                size_t a1 = a0 + (size_t)8 * DM;
                *(float2*)(g_ctx + a0) = make_float2(acc[mi][ni][0], acc[mi][ni][1]);
                *(float2*)(g_ctx + a1) = make_float2(acc[mi][ni][2], acc[mi][ni][3]);
            } else {
                int bh0 = m, bh1 = m + 8;
                size_t a0 = ((size_t)(bh0 >> 4) * SS_ + iE) * DM + (bh0 & 15) * DKV + ncol;
                size_t a1 = ((size_t)(bh1 >> 4) * SS_ + iE) * DM + (bh1 & 15) * DKV + ncol;
                *(float2*)(g_ctx2 + a0) = make_float2(acc[mi][ni][0], acc[mi][ni][1]);
                *(float2*)(g_ctx2 + a1) = make_float2(acc[mi][ni][2], acc[mi][ni][3]);
            }
        }
    }
}

// ===========================================================================
// Launcher — R7 topology: edge converts ∥ projections; content ∥ edge pairs.
// ===========================================================================
extern "C" void kernel_launch(void* const* d_in, const int* in_sizes, int n_in,
                              void* d_out, int out_size)
{
    const float* queries     = (const float*)d_in[0];
    const float* edges_key   = (const float*)d_in[1];
    const float* edges_value = (const float*)d_in[2];
    const float* attn_bias   = (const float*)d_in[3];
    const float* Wq = (const float*)d_in[4];
    const float* bq = (const float*)d_in[5];
    const float* Wk = (const float*)d_in[6];
    const float* bk = (const float*)d_in[7];
    const float* Wv = (const float*)d_in[8];
    const float* bv = (const float*)d_in[9];
    const float* Wo = (const float*)d_in[10];
    const float* bo = (const float*)d_in[11];
    float* out = (float*)d_out;

    static cudaStream_t s2 = nullptr, s3 = nullptr;
    static cudaEvent_t evFork = nullptr, evEdgeSplit = nullptr, evQKV = nullptr,
                       evEdgeSc = nullptr, evSM = nullptr, evCtx1 = nullptr;
    if (!s2) {
        cudaStreamCreateWithFlags(&s2, cudaStreamNonBlocking);
        cudaStreamCreateWithFlags(&s3, cudaStreamNonBlocking);
        cudaEventCreateWithFlags(&evFork,      cudaEventDisableTiming);
        cudaEventCreateWithFlags(&evEdgeSplit, cudaEventDisableTiming);
        cudaEventCreateWithFlags(&evQKV,       cudaEventDisableTiming);
        cudaEventCreateWithFlags(&evEdgeSc,    cudaEventDisableTiming);
        cudaEventCreateWithFlags(&evSM,        cudaEventDisableTiming);
        cudaEventCreateWithFlags(&evCtx1,      cudaEventDisableTiming);
    }

    cudaStream_t st = 0;
    cudaStreamCaptureStatus cs = cudaStreamCaptureStatusNone;
    if (cudaStreamIsCapturing(cudaStreamPerThread, &cs) == cudaSuccess &&
        cs == cudaStreamCaptureStatusActive)
        st = cudaStreamPerThread;

    // fork: edge-tensor converts overlap the projection path
    cudaEventRecord(evFork, st);
    cudaStreamWaitEvent(s2, evFork, 0);
    k_split_ek <<<8192, 256, 0, s2>>>(edges_key);
    k_split_evt<<<dim3(16, 2, 512), 256, 0, s2>>>(edges_value);
    cudaEventRecord(evEdgeSplit, s2);

    // projection path (main stream) — single fp16, K=1024
    k_split <<<2048, 256, 0, st>>>(queries, 0);
    k_wsplit<<<dim3(4, 128, 4), 256, 0, st>>>(Wq, Wk, Wv, Wo);
    k_gemm_f16<<<dim3(24, 32), 256, 0, st>>>(bq, bk, bv, nullptr, 0);
    cudaEventRecord(evQKV, st);

    // content scores (st) ∥ edge scores (s3) — fp16 component buffers
    cudaStreamWaitEvent(s3, evQKV, 0);
    cudaStreamWaitEvent(s3, evEdgeSplit, 0);
    k_scores<<<dim3(4, 512), 256, 0, s3>>>(1);
    cudaEventRecord(evEdgeSc, s3);

    k_scores<<<dim3(4, 4, 128), 256, 0, st>>>(0);

    // softmax reads both component buffers + fp32 bias
    cudaStreamWaitEvent(st, evEdgeSc, 0);
    k_softmax_split<<<8192, 256, 0, st>>>(attn_bias);
    cudaEventRecord(evSM, st);

    // content context (st) ∥ edge context (s3)
    cudaStreamWaitEvent(s3, evSM, 0);
    k_ctx<<<dim3(512), 256, 0, s3>>>(1);
    cudaEventRecord(evCtx1, s3);

    k_ctx<<<dim3(4, 128), 256, 0, st>>>(0);

    // output projection (needs both context buffers) — single fp16, K=1024
    cudaStreamWaitEvent(st, evCtx1, 0);
    k_split<<<2048, 256, 0, st>>>(nullptr, 1);
    k_gemm_f16<<<dim3(8, 32), 256, 0, st>>>(bo, nullptr, nullptr, out, 1);
}